// round 9
// baseline (speedup 1.0000x reference)
#include <cuda_runtime.h>
#include <cuda_fp16.h>
#include <cstdint>

// Problem constants
#define B_   16
#define S_   626
#define D_   768
#define H_   12
#define HD_  64
#define M_   (B_*S_)          // 10016
#define BH_  (B_*H_)          // 192
#define SM1_ (S_-1)           // 625
#define PSTR 644              // P row stride (floats)
#define QSH  72               // Qh/Kh/Vh half-tile row stride (halves)
#define QT   32               // q-tile rows in fused_attn
#define AST  24               // proj A tile k-stride (halves)
#define BST  136              // proj B tile n-stride (halves)

// Scratch (device globals; no cudaMalloc allowed)
__device__ float g_q[BH_*(size_t)S_*HD_];     // [b,h,s,hd]
__device__ float g_k[BH_*(size_t)S_*HD_];
__device__ float g_v[BH_*(size_t)S_*HD_];
__device__ float g_ctx[(size_t)M_*D_];        // [b,s, h*64+hd]
__device__ float g_contrib[BH_*S_];           // fixed scores col 0

// ---------------------------------------------------------------------------
// helpers
// ---------------------------------------------------------------------------
__device__ __forceinline__ void hmma(float c[4],
    uint32_t a0, uint32_t a1, uint32_t a2, uint32_t a3,
    uint32_t b0, uint32_t b1)
{
    asm volatile(
        "mma.sync.aligned.m16n8k16.row.col.f32.f16.f16.f32 "
        "{%0,%1,%2,%3}, {%4,%5,%6,%7}, {%8,%9}, {%0,%1,%2,%3};"
        : "+f"(c[0]), "+f"(c[1]), "+f"(c[2]), "+f"(c[3])
        : "r"(a0), "r"(a1), "r"(a2), "r"(a3), "r"(b0), "r"(b1));
}

__device__ __forceinline__ void ldsm_x4(
    uint32_t& r0, uint32_t& r1, uint32_t& r2, uint32_t& r3, const void* p)
{
    uint32_t a = (uint32_t)__cvta_generic_to_shared(p);
    asm volatile("ldmatrix.sync.aligned.m8n8.x4.shared.b16 {%0,%1,%2,%3}, [%4];"
        : "=r"(r0), "=r"(r1), "=r"(r2), "=r"(r3) : "r"(a));
}

__device__ __forceinline__ void ldsm_x4_t(
    uint32_t& r0, uint32_t& r1, uint32_t& r2, uint32_t& r3, const void* p)
{
    uint32_t a = (uint32_t)__cvta_generic_to_shared(p);
    asm volatile("ldmatrix.sync.aligned.m8n8.x4.trans.shared.b16 {%0,%1,%2,%3}, [%4];"
        : "=r"(r0), "=r"(r1), "=r"(r2), "=r"(r3) : "r"(a));
}

__device__ __forceinline__ uint4 pack8h(float4 a, float4 b) {
    uint4 u;
    __half2 h;
    h = __floats2half2_rn(a.x, a.y); u.x = *(uint32_t*)&h;
    h = __floats2half2_rn(a.z, a.w); u.y = *(uint32_t*)&h;
    h = __floats2half2_rn(b.x, b.y); u.z = *(uint32_t*)&h;
    h = __floats2half2_rn(b.z, b.w); u.w = *(uint32_t*)&h;
    return u;
}

__device__ __forceinline__ uint2 pack4h(float4 v) {
    uint2 u;
    __half2 h;
    h = __floats2half2_rn(v.x, v.y); u.x = *(uint32_t*)&h;
    h = __floats2half2_rn(v.z, v.w); u.y = *(uint32_t*)&h;
    return u;
}

__device__ __forceinline__ uint32_t packh2(float a, float b) {
    __half2 h = __floats2half2_rn(a, b);
    return *(uint32_t*)&h;
}

// ---------------------------------------------------------------------------
// Projection GEMM core (fp16 m16n8k16 + ldmatrix, 1 sync/iter). Unchanged R8.
// ---------------------------------------------------------------------------
template <bool QKV>
__device__ __forceinline__ void gemm_core(
    const float* __restrict__ Asrc, const float* __restrict__ W,
    const float* __restrict__ bias, float* __restrict__ dst,
    int m0, int n0,
    __half (*As)[128][AST], __half (*Bs)[16][BST])
{
    const int tid = threadIdx.x;
    const int wid = tid >> 5, lane = tid & 31;
    const int gid = lane >> 2, tk = lane & 3;
    const int wm = (wid & 1) * 64;
    const int wn = (wid >> 1) * 32;
    const int l15 = lane & 15, lhi = (lane >> 4) * 8;

    const int arow = tid >> 1, ak8 = (tid & 1) * 8;
    const int bkr  = tid >> 4, bn8 = (tid & 15) * 8;
    const bool aval = (m0 + arow < M_);

    float acc[4][4][4];
    #pragma unroll
    for (int mi = 0; mi < 4; mi++)
        #pragma unroll
        for (int ni = 0; ni < 4; ni++)
            #pragma unroll
            for (int r = 0; r < 4; r++) acc[mi][ni][r] = 0.f;

    {
        float4 va0 = make_float4(0,0,0,0), va1 = make_float4(0,0,0,0);
        if (aval) {
            va0 = *(const float4*)(Asrc + (size_t)(m0 + arow) * D_ + ak8);
            va1 = *(const float4*)(Asrc + (size_t)(m0 + arow) * D_ + ak8 + 4);
        }
        float4 vb0 = *(const float4*)(W + (size_t)bkr * D_ + n0 + bn8);
        float4 vb1 = *(const float4*)(W + (size_t)bkr * D_ + n0 + bn8 + 4);
        *(uint4*)&As[0][arow][ak8] = pack8h(va0, va1);
        *(uint4*)&Bs[0][bkr][bn8]  = pack8h(vb0, vb1);
    }
    __syncthreads();

    const int NK = D_ / 16;   // 48
    for (int kt = 0; kt < NK; kt++) {
        const int cur = kt & 1;
        const bool pf = (kt + 1 < NK);
        float4 va0, va1, vb0, vb1;
        if (pf) {
            const int k1 = (kt + 1) * 16;
            va0 = va1 = make_float4(0,0,0,0);
            if (aval) {
                va0 = *(const float4*)(Asrc + (size_t)(m0 + arow) * D_ + k1 + ak8);
                va1 = *(const float4*)(Asrc + (size_t)(m0 + arow) * D_ + k1 + ak8 + 4);
            }
            vb0 = *(const float4*)(W + (size_t)(k1 + bkr) * D_ + n0 + bn8);
            vb1 = *(const float4*)(W + (size_t)(k1 + bkr) * D_ + n0 + bn8 + 4);
        }

        uint32_t af[4][4];
        #pragma unroll
        for (int mi = 0; mi < 4; mi++)
            ldsm_x4(af[mi][0], af[mi][1], af[mi][2], af[mi][3],
                    &As[cur][wm + mi * 16 + l15][lhi]);
        uint32_t bf[8];
        ldsm_x4_t(bf[0], bf[1], bf[2], bf[3], &Bs[cur][l15][wn + lhi]);
        ldsm_x4_t(bf[4], bf[5], bf[6], bf[7], &Bs[cur][l15][wn + 16 + lhi]);

        #pragma unroll
        for (int mi = 0; mi < 4; mi++) {
            hmma(acc[mi][0], af[mi][0], af[mi][1], af[mi][2], af[mi][3], bf[0], bf[1]);
            hmma(acc[mi][1], af[mi][0], af[mi][1], af[mi][2], af[mi][3], bf[2], bf[3]);
            hmma(acc[mi][2], af[mi][0], af[mi][1], af[mi][2], af[mi][3], bf[4], bf[5]);
            hmma(acc[mi][3], af[mi][0], af[mi][1], af[mi][2], af[mi][3], bf[6], bf[7]);
        }

        if (pf) {
            *(uint4*)&As[cur ^ 1][arow][ak8] = pack8h(va0, va1);
            *(uint4*)&Bs[cur ^ 1][bkr][bn8]  = pack8h(vb0, vb1);
        }
        __syncthreads();
    }

    #pragma unroll
    for (int mi = 0; mi < 4; mi++) {
        #pragma unroll
        for (int ni = 0; ni < 4; ni++) {
            const int col = n0 + wn + ni * 8 + 2 * tk;
            const float b0v = bias[col], b1v = bias[col + 1];
            const int r0 = m0 + wm + mi * 16 + gid;
            const int r1 = r0 + 8;
            if (QKV) {
                const int h = col >> 6, hd = col & 63;
                if (r0 < M_) {
                    const int b = r0 / S_, s = r0 - b * S_;
                    *(float2*)(dst + (((size_t)(b * H_ + h)) * S_ + s) * HD_ + hd) =
                        make_float2(acc[mi][ni][0] + b0v, acc[mi][ni][1] + b1v);
                }
                if (r1 < M_) {
                    const int b = r1 / S_, s = r1 - b * S_;
                    *(float2*)(dst + (((size_t)(b * H_ + h)) * S_ + s) * HD_ + hd) =
                        make_float2(acc[mi][ni][2] + b0v, acc[mi][ni][3] + b1v);
                }
            } else {
                if (r0 < M_)
                    *(float2*)(dst + (size_t)r0 * D_ + col) =
                        make_float2(acc[mi][ni][0] + b0v, acc[mi][ni][1] + b1v);
                if (r1 < M_)
                    *(float2*)(dst + (size_t)r1 * D_ + col) =
                        make_float2(acc[mi][ni][2] + b0v, acc[mi][ni][3] + b1v);
            }
        }
    }
}

__global__ __launch_bounds__(256, 2) void gemm_qkv(
    const float* __restrict__ X,
    const float* __restrict__ Wq, const float* __restrict__ bq,
    const float* __restrict__ Wk, const float* __restrict__ bk,
    const float* __restrict__ Wv, const float* __restrict__ bv)
{
    __shared__ __align__(16) __half As[2][128][AST];
    __shared__ __align__(16) __half Bs[2][16][BST];
    const int m0  = blockIdx.x * 128;
    const int ng  = blockIdx.y * 128;
    const int mat = ng / D_;
    const int n0  = ng - mat * D_;
    const float* W    = (mat == 0) ? Wq : (mat == 1) ? Wk : Wv;
    const float* bias = (mat == 0) ? bq : (mat == 1) ? bk : bv;
    float* dst        = (mat == 0) ? g_q : (mat == 1) ? g_k : g_v;
    gemm_core<true>(X, W, bias, dst, m0, n0, As, Bs);
}

__global__ __launch_bounds__(256, 2) void gemm_out(
    const float* __restrict__ W, const float* __restrict__ bias,
    float* __restrict__ out)
{
    __shared__ __align__(16) __half As[2][128][AST];
    __shared__ __align__(16) __half Bs[2][16][BST];
    gemm_core<false>(g_ctx, W, bias, out, blockIdx.x * 128, blockIdx.y * 128, As, Bs);
}

// ---------------------------------------------------------------------------
// Fused attention, 32-row q tile, fp16 MMA for scores and ctx.
//   scores: Qh[m][k] x Kh[n][k] -> P f32 (x0.125)
//   softmax in P (f32, exact as before) + contrib capture + probs gmem write
//   ctx: P (f32->half regs) x Vh[k][n] -> g_ctx
// SMEM: P[32][644] f32 + Qh[32][QSH] + KVh[64][QSH]  (~94 KB, 2 blocks/SM)
// ---------------------------------------------------------------------------
__global__ __launch_bounds__(256) void fused_attn(
    float* __restrict__ probs, const int* __restrict__ mask)
{
    extern __shared__ float sm[];
    float*  P  = sm;                                   // [QT][PSTR]
    __half* Qh = (__half*)(sm + QT * PSTR);            // [QT][QSH]
    __half* KV = Qh + QT * QSH;                        // [64][QSH]

    const int bh  = blockIdx.y;
    const int m0  = blockIdx.x * QT;
    const int tid = threadIdx.x;
    const int wid = tid >> 5, lane = tid & 31;
    const int gid = lane >> 2, tk = lane & 3;
    const int wm  = (wid & 1) * 16;     // 2 warps along m (16 rows each)
    const int wn  = (wid >> 1) * 16;    // 4 warps along n (16 cols each)
    const int l15 = lane & 15, lhi = (lane >> 4) * 8;
    // B-operand (non-trans LDSM on [n][k]) per-lane addressing
    const int brow = (lane & 7) + ((lane & 16) ? 8 : 0);
    const int bko  = (lane & 8) ? 8 : 0;
    const int b   = bh / H_;
    const int h   = bh - b * H_;

    const float* qb = g_q + (size_t)bh * S_ * HD_;
    const float* kb = g_k + (size_t)bh * S_ * HD_;
    const float* vb = g_v + (size_t)bh * S_ * HD_;
    float* pgm = probs + (size_t)bh * S_ * S_;

    // zero pad columns 626..PSTR-1 of P
    for (int i = tid; i < QT * (PSTR - S_); i += 256) {
        const int r = i / (PSTR - S_);
        const int c = S_ + i - r * (PSTR - S_);
        P[r * PSTR + c] = 0.f;
    }

    // load Q tile (QT rows x 64) as half
    #pragma unroll
    for (int i = 0; i < 2; i++) {
        const int idx = tid + i * 256;
        const int row = idx >> 4, c4 = (idx & 15) << 2;
        float4 v = make_float4(0.f, 0.f, 0.f, 0.f);
        if (m0 + row < S_) v = *(const float4*)(qb + (size_t)(m0 + row) * HD_ + c4);
        *(uint2*)&Qh[row * QSH + c4] = pack4h(v);
    }

    // ---- scores phase: P[QT][626] = (Q @ K^T) * 0.125, fp16 MMA ----
    for (int nc = 0; nc < 10; nc++) {
        const int n0 = nc * 64;
        __syncthreads();
        #pragma unroll
        for (int i = 0; i < 4; i++) {
            const int idx = tid + i * 256;
            const int row = idx >> 4, c4 = (idx & 15) << 2;
            float4 v = make_float4(0.f, 0.f, 0.f, 0.f);
            if (n0 + row < S_) v = *(const float4*)(kb + (size_t)(n0 + row) * HD_ + c4);
            *(uint2*)&KV[row * QSH + c4] = pack4h(v);   // Kh: [n][k]
        }
        __syncthreads();

        float acc[2][4];
        #pragma unroll
        for (int ni = 0; ni < 2; ni++)
            #pragma unroll
            for (int r = 0; r < 4; r++) acc[ni][r] = 0.f;

        #pragma unroll
        for (int ks = 0; ks < 64; ks += 16) {
            uint32_t a0, a1, a2, a3;
            ldsm_x4(a0, a1, a2, a3, &Qh[(wm + l15) * QSH + ks + lhi]);
            uint32_t b0, b1, b2, b3;
            ldsm_x4(b0, b1, b2, b3, &KV[(wn + brow) * QSH + ks + bko]);
            hmma(acc[0], a0, a1, a2, a3, b0, b1);
            hmma(acc[1], a0, a1, a2, a3, b2, b3);
        }

        #pragma unroll
        for (int ni = 0; ni < 2; ni++) {
            const int col = n0 + wn + ni * 8 + 2 * tk;   // even
            if (col < S_) {
                *(float2*)&P[(wm + gid    ) * PSTR + col] =
                    make_float2(acc[ni][0] * 0.125f, acc[ni][1] * 0.125f);
                *(float2*)&P[(wm + gid + 8) * PSTR + col] =
                    make_float2(acc[ni][2] * 0.125f, acc[ni][3] * 0.125f);
            }
        }
    }
    __syncthreads();

    // ---- softmax phase (f32, unchanged): warp w owns rows w*4..w*4+3 ----
    for (int r = wid * 4; r < wid * 4 + 4; r++) {
        const int q = m0 + r;
        if (q >= S_) break;
        float* row = P + r * PSTR;

        float mx = -3.4e38f;
        for (int i = lane; i < S_; i += 32) mx = fmaxf(mx, row[i]);
        #pragma unroll
        for (int o = 16; o; o >>= 1) mx = fmaxf(mx, __shfl_xor_sync(0xffffffffu, mx, o));

        if (q == 0) {
            const float add = mx * 0.25f;
            for (int i = lane; i < S_; i += 32) {
                const int mk = (i == 0) ? 0 : mask[b * SM1_ + i - 1];
                if (mk == 0) row[i] += add;
            }
            __syncwarp();
            mx = -3.4e38f;
            for (int i = lane; i < S_; i += 32) mx = fmaxf(mx, row[i]);
            #pragma unroll
            for (int o = 16; o; o >>= 1) mx = fmaxf(mx, __shfl_xor_sync(0xffffffffu, mx, o));
        }

        if (lane == 0) g_contrib[(size_t)bh * S_ + q] = row[0];

        float s = 0.f;
        for (int i = lane; i < S_; i += 32) {
            const float e = expf(row[i] - mx);
            row[i] = e;
            s += e;
        }
        #pragma unroll
        for (int o = 16; o; o >>= 1) s += __shfl_xor_sync(0xffffffffu, s, o);
        const float inv = 1.0f / s;

        float* prow = pgm + (size_t)q * S_;
        for (int i = lane; i < S_; i += 32) {
            const float p = row[i] * inv;
            row[i] = p;
            prow[i] = p;
        }
    }
    __syncthreads();

    // ---- ctx phase: ctx[QT][64] = P[QT][626] @ V[626][64], fp16 MMA ----
    float cacc[2][4];
    #pragma unroll
    for (int ni = 0; ni < 2; ni++)
        #pragma unroll
        for (int r = 0; r < 4; r++) cacc[ni][r] = 0.f;

    for (int kc = 0; kc < 10; kc++) {
        const int k0 = kc * 64;
        __syncthreads();
        #pragma unroll
        for (int i = 0; i < 4; i++) {
            const int idx = tid + i * 256;
            const int row = idx >> 4, c4 = (idx & 15) << 2;
            float4 v = make_float4(0.f, 0.f, 0.f, 0.f);
            if (k0 + row < S_) v = *(const float4*)(vb + (size_t)(k0 + row) * HD_ + c4);
            *(uint2*)&KV[row * QSH + c4] = pack4h(v);   // Vh: [k][n]
        }
        __syncthreads();

        #pragma unroll
        for (int ks = 0; ks < 64; ks += 16) {
            const float* pr0 = P + (wm + gid    ) * PSTR + k0 + ks + 2 * tk;
            const float* pr1 = P + (wm + gid + 8) * PSTR + k0 + ks + 2 * tk;
            float2 v0 = *(const float2*)pr0;
            float2 v1 = *(const float2*)pr1;
            float2 v2 = *(const float2*)(pr0 + 8);
            float2 v3 = *(const float2*)(pr1 + 8);
            const uint32_t a0 = packh2(v0.x, v0.y);
            const uint32_t a1 = packh2(v1.x, v1.y);
            const uint32_t a2 = packh2(v2.x, v2.y);
            const uint32_t a3 = packh2(v3.x, v3.y);
            uint32_t b0, b1, b2, b3;
            ldsm_x4_t(b0, b1, b2, b3, &KV[(ks + l15) * QSH + wn + lhi]);
            hmma(cacc[0], a0, a1, a2, a3, b0, b1);
            hmma(cacc[1], a0, a1, a2, a3, b2, b3);
        }
    }

    #pragma unroll
    for (int ni = 0; ni < 2; ni++) {
        const int col = wn + ni * 8 + 2 * tk;   // 0..62
        const int r0 = m0 + wm + gid;
        const int r1 = r0 + 8;
        if (r0 < S_)
            *(float2*)(g_ctx + ((size_t)(b * S_ + r0)) * D_ + h * HD_ + col) =
                make_float2(cacc[ni][0], cacc[ni][1]);
        if (r1 < S_)
            *(float2*)(g_ctx + ((size_t)(b * S_ + r1)) * D_ + h * HD_ + col) =
                make_float2(cacc[ni][2], cacc[ni][3]);
    }
}

// ---------------------------------------------------------------------------
// Contribution: softmax over q of g_contrib[bh, :]
// ---------------------------------------------------------------------------
__global__ __launch_bounds__(256) void contrib_kernel(float* __restrict__ out)
{
    const int bh = blockIdx.x;
    const float* src = g_contrib + (size_t)bh * S_;
    __shared__ float red[8];
    const int tid = threadIdx.x;

    float m = -3.4e38f;
    for (int i = tid; i < S_; i += 256) m = fmaxf(m, src[i]);
    #pragma unroll
    for (int o = 16; o; o >>= 1) m = fmaxf(m, __shfl_xor_sync(0xffffffffu, m, o));
    if ((tid & 31) == 0) red[tid >> 5] = m;
    __syncthreads();
    if (tid == 0) {
        float mm = red[0];
        #pragma unroll
        for (int w = 1; w < 8; w++) mm = fmaxf(mm, red[w]);
        red[0] = mm;
    }
    __syncthreads();
    m = red[0];
    __syncthreads();

    float s = 0.f;
    for (int i = tid; i < S_; i += 256) s += expf(src[i] - m);
    #pragma unroll
    for (int o = 16; o; o >>= 1) s += __shfl_xor_sync(0xffffffffu, s, o);
    if ((tid & 31) == 0) red[tid >> 5] = s;
    __syncthreads();
    if (tid == 0) {
        float ss = 0.f;
        #pragma unroll
        for (int w = 0; w < 8; w++) ss += red[w];
        red[0] = ss;
    }
    __syncthreads();
    const float inv = 1.0f / red[0];
    for (int i = tid; i < S_; i += 256)
        out[(size_t)bh * S_ + i] = expf(src[i] - m) * inv;
}

// ---------------------------------------------------------------------------
// Launch
// ---------------------------------------------------------------------------
extern "C" void kernel_launch(void* const* d_in, const int* in_sizes, int n_in,
                              void* d_out, int out_size)
{
    const float* hs = (const float*)d_in[0];
    const int*  mask = (const int*) d_in[1];
    const float* Wq = (const float*)d_in[2];
    const float* bq = (const float*)d_in[3];
    const float* Wk = (const float*)d_in[4];
    const float* bk = (const float*)d_in[5];
    const float* Wv = (const float*)d_in[6];
    const float* bv = (const float*)d_in[7];
    const float* Wo = (const float*)d_in[8];
    const float* bo = (const float*)d_in[9];

    float* out     = (float*)d_out;
    float* att_out = out;                                       // [B,S,D]
    float* probs   = out + (size_t)M_ * D_;                     // [B,H,S,S]
    float* contrib = probs + (size_t)BH_ * S_ * S_;             // [B,H,S]

    const int smem_bytes = QT * PSTR * 4 + QT * QSH * 2 + 64 * QSH * 2;
    cudaFuncSetAttribute(fused_attn,
        cudaFuncAttributeMaxDynamicSharedMemorySize, smem_bytes);

    gemm_qkv<<<dim3(79, 18), 256>>>(hs, Wq, bq, Wk, bk, Wv, bv);
    fused_attn<<<dim3(20, 192), 256, smem_bytes>>>(probs, mask);
    contrib_kernel<<<BH_, 256>>>(contrib);
    gemm_out<<<dim3(79, 6), 256>>>(Wo, bo, att_out);
}

// round 10
// speedup vs baseline: 1.1528x; 1.1528x over previous
#include <cuda_runtime.h>
#include <cuda_fp16.h>
#include <cstdint>

// Problem constants
#define B_   16
#define S_   626
#define D_   768
#define H_   12
#define HD_  64
#define M_   (B_*S_)          // 10016
#define BH_  (B_*H_)          // 192
#define SM1_ (S_-1)           // 625
#define PSTR 644              // P row stride (floats)
#define QSTR 68               // Q/K tile row stride (floats)
#define VSTR 72               // V tile row stride
#define QT   32               // q-tile rows in fused_attn
#define AST  24               // proj A tile k-stride (halves)
#define BST  136              // proj B tile n-stride (halves)

// Scratch (device globals; no cudaMalloc allowed)
__device__ float  g_q[BH_*(size_t)S_*HD_];      // [b,h,s,hd] f32
__device__ float  g_k[BH_*(size_t)S_*HD_];
__device__ float  g_v[BH_*(size_t)S_*HD_];
__device__ __half g_ctxh[(size_t)M_*D_];        // ctx as half
__device__ __half g_xh[(size_t)M_*D_];          // hidden_states as half
__device__ __half g_wq[D_*D_], g_wk[D_*D_], g_wv[D_*D_], g_wo[D_*D_];
__device__ float  g_contrib[BH_*S_];            // fixed scores col 0

// ---------------------------------------------------------------------------
// helpers
// ---------------------------------------------------------------------------
__device__ __forceinline__ uint32_t f2t(float x) {
    uint32_t r;
    asm("cvt.rna.tf32.f32 %0, %1;" : "=r"(r) : "f"(x));
    return r;
}

__device__ __forceinline__ void mma_tf32(float c[4],
    uint32_t a0, uint32_t a1, uint32_t a2, uint32_t a3,
    uint32_t b0, uint32_t b1)
{
    asm volatile(
        "mma.sync.aligned.m16n8k8.row.col.f32.tf32.tf32.f32 "
        "{%0,%1,%2,%3}, {%4,%5,%6,%7}, {%8,%9}, {%0,%1,%2,%3};"
        : "+f"(c[0]), "+f"(c[1]), "+f"(c[2]), "+f"(c[3])
        : "r"(a0), "r"(a1), "r"(a2), "r"(a3), "r"(b0), "r"(b1));
}

__device__ __forceinline__ void hmma(float c[4],
    uint32_t a0, uint32_t a1, uint32_t a2, uint32_t a3,
    uint32_t b0, uint32_t b1)
{
    asm volatile(
        "mma.sync.aligned.m16n8k16.row.col.f32.f16.f16.f32 "
        "{%0,%1,%2,%3}, {%4,%5,%6,%7}, {%8,%9}, {%0,%1,%2,%3};"
        : "+f"(c[0]), "+f"(c[1]), "+f"(c[2]), "+f"(c[3])
        : "r"(a0), "r"(a1), "r"(a2), "r"(a3), "r"(b0), "r"(b1));
}

__device__ __forceinline__ void ldsm_x4(
    uint32_t& r0, uint32_t& r1, uint32_t& r2, uint32_t& r3, const void* p)
{
    uint32_t a = (uint32_t)__cvta_generic_to_shared(p);
    asm volatile("ldmatrix.sync.aligned.m8n8.x4.shared.b16 {%0,%1,%2,%3}, [%4];"
        : "=r"(r0), "=r"(r1), "=r"(r2), "=r"(r3) : "r"(a));
}

__device__ __forceinline__ void ldsm_x4_t(
    uint32_t& r0, uint32_t& r1, uint32_t& r2, uint32_t& r3, const void* p)
{
    uint32_t a = (uint32_t)__cvta_generic_to_shared(p);
    asm volatile("ldmatrix.sync.aligned.m8n8.x4.trans.shared.b16 {%0,%1,%2,%3}, [%4];"
        : "=r"(r0), "=r"(r1), "=r"(r2), "=r"(r3) : "r"(a));
}

__device__ __forceinline__ uint2 pack4h(float4 v) {
    uint2 u;
    __half2 h;
    h = __floats2half2_rn(v.x, v.y); u.x = *(uint32_t*)&h;
    h = __floats2half2_rn(v.z, v.w); u.y = *(uint32_t*)&h;
    return u;
}

__device__ __forceinline__ uint32_t packh2(float a, float b) {
    __half2 h = __floats2half2_rn(a, b);
    return *(uint32_t*)&h;
}

// ---------------------------------------------------------------------------
// f32 -> f16 bulk conversion (vectorized, grid-stride)
// ---------------------------------------------------------------------------
__global__ __launch_bounds__(256) void f2h4(
    const float* __restrict__ src, __half* __restrict__ dst, int n4)
{
    for (int i = blockIdx.x * 256 + threadIdx.x; i < n4; i += gridDim.x * 256) {
        float4 v = ((const float4*)src)[i];
        ((uint2*)dst)[i] = pack4h(v);
    }
}

// ---------------------------------------------------------------------------
// Projection GEMM core (fp16 m16n8k16 + ldmatrix, half gmem operands,
// 1 sync/iter, reg double buffer). Block 128x128, BK=16, warp tile 64x32.
// ---------------------------------------------------------------------------
template <bool QKV>
__device__ __forceinline__ void gemm_core(
    const __half* __restrict__ Asrc, const __half* __restrict__ W,
    const float* __restrict__ bias, float* __restrict__ dst,
    int m0, int n0,
    __half (*As)[128][AST], __half (*Bs)[16][BST])
{
    const int tid = threadIdx.x;
    const int wid = tid >> 5, lane = tid & 31;
    const int gid = lane >> 2, tk = lane & 3;
    const int wm = (wid & 1) * 64;
    const int wn = (wid >> 1) * 32;
    const int l15 = lane & 15, lhi = (lane >> 4) * 8;

    const int arow = tid >> 1, ak8 = (tid & 1) * 8;   // A: one uint4/thread
    const int bkr  = tid >> 4, bn8 = (tid & 15) * 8;  // B: one uint4/thread
    const bool aval = (m0 + arow < M_);

    float acc[4][4][4];
    #pragma unroll
    for (int mi = 0; mi < 4; mi++)
        #pragma unroll
        for (int ni = 0; ni < 4; ni++)
            #pragma unroll
            for (int r = 0; r < 4; r++) acc[mi][ni][r] = 0.f;

    const uint4 z4 = make_uint4(0u, 0u, 0u, 0u);

    // prologue: fill stage 0
    {
        uint4 va = z4;
        if (aval) va = *(const uint4*)(Asrc + (size_t)(m0 + arow) * D_ + ak8);
        uint4 vb = *(const uint4*)(W + (size_t)bkr * D_ + n0 + bn8);
        *(uint4*)&As[0][arow][ak8] = va;
        *(uint4*)&Bs[0][bkr][bn8]  = vb;
    }
    __syncthreads();

    const int NK = D_ / 16;   // 48
    for (int kt = 0; kt < NK; kt++) {
        const int cur = kt & 1;
        const bool pf = (kt + 1 < NK);
        uint4 va = z4, vb = z4;
        if (pf) {
            const int k1 = (kt + 1) * 16;
            if (aval) va = *(const uint4*)(Asrc + (size_t)(m0 + arow) * D_ + k1 + ak8);
            vb = *(const uint4*)(W + (size_t)(k1 + bkr) * D_ + n0 + bn8);
        }

        uint32_t af[4][4];
        #pragma unroll
        for (int mi = 0; mi < 4; mi++)
            ldsm_x4(af[mi][0], af[mi][1], af[mi][2], af[mi][3],
                    &As[cur][wm + mi * 16 + l15][lhi]);
        uint32_t bf[8];
        ldsm_x4_t(bf[0], bf[1], bf[2], bf[3], &Bs[cur][l15][wn + lhi]);
        ldsm_x4_t(bf[4], bf[5], bf[6], bf[7], &Bs[cur][l15][wn + 16 + lhi]);

        #pragma unroll
        for (int mi = 0; mi < 4; mi++) {
            hmma(acc[mi][0], af[mi][0], af[mi][1], af[mi][2], af[mi][3], bf[0], bf[1]);
            hmma(acc[mi][1], af[mi][0], af[mi][1], af[mi][2], af[mi][3], bf[2], bf[3]);
            hmma(acc[mi][2], af[mi][0], af[mi][1], af[mi][2], af[mi][3], bf[4], bf[5]);
            hmma(acc[mi][3], af[mi][0], af[mi][1], af[mi][2], af[mi][3], bf[6], bf[7]);
        }

        if (pf) {
            *(uint4*)&As[cur ^ 1][arow][ak8] = va;
            *(uint4*)&Bs[cur ^ 1][bkr][bn8]  = vb;
        }
        __syncthreads();
    }

    // epilogue
    #pragma unroll
    for (int mi = 0; mi < 4; mi++) {
        #pragma unroll
        for (int ni = 0; ni < 4; ni++) {
            const int col = n0 + wn + ni * 8 + 2 * tk;
            const float b0v = bias[col], b1v = bias[col + 1];
            const int r0 = m0 + wm + mi * 16 + gid;
            const int r1 = r0 + 8;
            if (QKV) {
                const int h = col >> 6, hd = col & 63;
                float* dq = dst;   // g_q/g_k/g_v selected by caller
                if (r0 < M_) {
                    const int b = r0 / S_, s = r0 - b * S_;
                    *(float2*)(dq + (((size_t)(b * H_ + h)) * S_ + s) * HD_ + hd) =
                        make_float2(acc[mi][ni][0] + b0v, acc[mi][ni][1] + b1v);
                }
                if (r1 < M_) {
                    const int b = r1 / S_, s = r1 - b * S_;
                    *(float2*)(dq + (((size_t)(b * H_ + h)) * S_ + s) * HD_ + hd) =
                        make_float2(acc[mi][ni][2] + b0v, acc[mi][ni][3] + b1v);
                }
            } else {
                if (r0 < M_)
                    *(float2*)(dst + (size_t)r0 * D_ + col) =
                        make_float2(acc[mi][ni][0] + b0v, acc[mi][ni][1] + b1v);
                if (r1 < M_)
                    *(float2*)(dst + (size_t)r1 * D_ + col) =
                        make_float2(acc[mi][ni][2] + b0v, acc[mi][ni][3] + b1v);
            }
        }
    }
}

__global__ __launch_bounds__(256, 2) void gemm_qkv(
    const float* __restrict__ bq, const float* __restrict__ bk,
    const float* __restrict__ bv)
{
    __shared__ __align__(16) __half As[2][128][AST];
    __shared__ __align__(16) __half Bs[2][16][BST];
    const int m0  = blockIdx.x * 128;
    const int ng  = blockIdx.y * 128;
    const int mat = ng / D_;
    const int n0  = ng - mat * D_;
    const __half* W   = (mat == 0) ? g_wq : (mat == 1) ? g_wk : g_wv;
    const float* bias = (mat == 0) ? bq : (mat == 1) ? bk : bv;
    float* dst        = (mat == 0) ? g_q : (mat == 1) ? g_k : g_v;
    gemm_core<true>(g_xh, W, bias, dst, m0, n0, As, Bs);
}

__global__ __launch_bounds__(256, 2) void gemm_out(
    const float* __restrict__ bias, float* __restrict__ out)
{
    __shared__ __align__(16) __half As[2][128][AST];
    __shared__ __align__(16) __half Bs[2][16][BST];
    gemm_core<false>(g_ctxh, g_wo, bias, out, blockIdx.x * 128, blockIdx.y * 128, As, Bs);
}

// ---------------------------------------------------------------------------
// Fused attention, 32-row q tile (tf32 — R8-proven), ctx written as half.
// ---------------------------------------------------------------------------
__global__ __launch_bounds__(256) void fused_attn(
    float* __restrict__ probs, const int* __restrict__ mask)
{
    extern __shared__ float sm[];
    float*    P  = sm;                                   // [QT][PSTR]
    uint32_t* Qs = (uint32_t*)(sm + QT * PSTR);          // [QT][QSTR]
    uint32_t* KV = Qs + QT * QSTR;                       // K [64][QSTR] / V [64][VSTR]

    const int bh  = blockIdx.y;
    const int m0  = blockIdx.x * QT;
    const int tid = threadIdx.x;
    const int wid = tid >> 5, lane = tid & 31;
    const int gid = lane >> 2, tk = lane & 3;
    const int wm  = (wid & 1) * 16;
    const int wn  = (wid >> 1) * 16;
    const int b   = bh / H_;
    const int h   = bh - b * H_;

    const float* qb = g_q + (size_t)bh * S_ * HD_;
    const float* kb = g_k + (size_t)bh * S_ * HD_;
    const float* vb = g_v + (size_t)bh * S_ * HD_;
    float* pgm = probs + (size_t)bh * S_ * S_;

    for (int i = tid; i < QT * (PSTR - S_); i += 256) {
        const int r = i / (PSTR - S_);
        const int c = S_ + i - r * (PSTR - S_);
        P[r * PSTR + c] = 0.f;
    }

    #pragma unroll
    for (int i = 0; i < 2; i++) {
        const int idx = tid + i * 256;
        const int row = idx >> 4, c4 = (idx & 15) << 2;
        float4 v = make_float4(0.f, 0.f, 0.f, 0.f);
        if (m0 + row < S_) v = *(const float4*)(qb + (size_t)(m0 + row) * HD_ + c4);
        uint4 t;
        t.x = f2t(v.x); t.y = f2t(v.y); t.z = f2t(v.z); t.w = f2t(v.w);
        *(uint4*)&Qs[row * QSTR + c4] = t;
    }

    for (int nc = 0; nc < 10; nc++) {
        const int n0 = nc * 64;
        __syncthreads();
        #pragma unroll
        for (int i = 0; i < 4; i++) {
            const int idx = tid + i * 256;
            const int row = idx >> 4, c4 = (idx & 15) << 2;
            float4 v = make_float4(0.f, 0.f, 0.f, 0.f);
            if (n0 + row < S_) v = *(const float4*)(kb + (size_t)(n0 + row) * HD_ + c4);
            uint4 t;
            t.x = f2t(v.x); t.y = f2t(v.y); t.z = f2t(v.z); t.w = f2t(v.w);
            *(uint4*)&KV[row * QSTR + c4] = t;
        }
        __syncthreads();

        float acc[2][4];
        #pragma unroll
        for (int ni = 0; ni < 2; ni++)
            #pragma unroll
            for (int r = 0; r < 4; r++) acc[ni][r] = 0.f;

        #pragma unroll
        for (int ks = 0; ks < 64; ks += 8) {
            const uint32_t a0 = Qs[(wm + gid    ) * QSTR + ks + tk];
            const uint32_t a1 = Qs[(wm + gid + 8) * QSTR + ks + tk];
            const uint32_t a2 = Qs[(wm + gid    ) * QSTR + ks + tk + 4];
            const uint32_t a3 = Qs[(wm + gid + 8) * QSTR + ks + tk + 4];
            #pragma unroll
            for (int ni = 0; ni < 2; ni++) {
                const int nb = wn + ni * 8 + gid;
                mma_tf32(acc[ni], a0, a1, a2, a3,
                         KV[nb * QSTR + ks + tk], KV[nb * QSTR + ks + tk + 4]);
            }
        }

        #pragma unroll
        for (int ni = 0; ni < 2; ni++) {
            const int col = n0 + wn + ni * 8 + 2 * tk;
            if (col < S_) {
                *(float2*)&P[(wm + gid    ) * PSTR + col] =
                    make_float2(acc[ni][0] * 0.125f, acc[ni][1] * 0.125f);
                *(float2*)&P[(wm + gid + 8) * PSTR + col] =
                    make_float2(acc[ni][2] * 0.125f, acc[ni][3] * 0.125f);
            }
        }
    }
    __syncthreads();

    for (int r = wid * 4; r < wid * 4 + 4; r++) {
        const int q = m0 + r;
        if (q >= S_) break;
        float* row = P + r * PSTR;

        float mx = -3.4e38f;
        for (int i = lane; i < S_; i += 32) mx = fmaxf(mx, row[i]);
        #pragma unroll
        for (int o = 16; o; o >>= 1) mx = fmaxf(mx, __shfl_xor_sync(0xffffffffu, mx, o));

        if (q == 0) {
            const float add = mx * 0.25f;
            for (int i = lane; i < S_; i += 32) {
                const int mk = (i == 0) ? 0 : mask[b * SM1_ + i - 1];
                if (mk == 0) row[i] += add;
            }
            __syncwarp();
            mx = -3.4e38f;
            for (int i = lane; i < S_; i += 32) mx = fmaxf(mx, row[i]);
            #pragma unroll
            for (int o = 16; o; o >>= 1) mx = fmaxf(mx, __shfl_xor_sync(0xffffffffu, mx, o));
        }

        if (lane == 0) g_contrib[(size_t)bh * S_ + q] = row[0];

        float s = 0.f;
        for (int i = lane; i < S_; i += 32) {
            const float e = expf(row[i] - mx);
            row[i] = e;
            s += e;
        }
        #pragma unroll
        for (int o = 16; o; o >>= 1) s += __shfl_xor_sync(0xffffffffu, s, o);
        const float inv = 1.0f / s;

        float* prow = pgm + (size_t)q * S_;
        for (int i = lane; i < S_; i += 32) {
            const float p = row[i] * inv;
            row[i] = p;
            prow[i] = p;
        }
    }
    __syncthreads();

    float cacc[2][4];
    #pragma unroll
    for (int ni = 0; ni < 2; ni++)
        #pragma unroll
        for (int r = 0; r < 4; r++) cacc[ni][r] = 0.f;

    for (int kc = 0; kc < 10; kc++) {
        const int k0 = kc * 64;
        __syncthreads();
        #pragma unroll
        for (int i = 0; i < 4; i++) {
            const int idx = tid + i * 256;
            const int row = idx >> 4, c4 = (idx & 15) << 2;
            float4 v = make_float4(0.f, 0.f, 0.f, 0.f);
            if (k0 + row < S_) v = *(const float4*)(vb + (size_t)(k0 + row) * HD_ + c4);
            uint4 t;
            t.x = f2t(v.x); t.y = f2t(v.y); t.z = f2t(v.z); t.w = f2t(v.w);
            *(uint4*)&KV[row * VSTR + c4] = t;
        }
        __syncthreads();

        #pragma unroll
        for (int ks = 0; ks < 64; ks += 8) {
            const uint32_t a0 = f2t(P[(wm + gid    ) * PSTR + k0 + ks + tk]);
            const uint32_t a1 = f2t(P[(wm + gid + 8) * PSTR + k0 + ks + tk]);
            const uint32_t a2 = f2t(P[(wm + gid    ) * PSTR + k0 + ks + tk + 4]);
            const uint32_t a3 = f2t(P[(wm + gid + 8) * PSTR + k0 + ks + tk + 4]);
            #pragma unroll
            for (int ni = 0; ni < 2; ni++) {
                mma_tf32(cacc[ni], a0, a1, a2, a3,
                         KV[(ks + tk    ) * VSTR + wn + ni * 8 + gid],
                         KV[(ks + tk + 4) * VSTR + wn + ni * 8 + gid]);
            }
        }
    }

    // ctx epilogue -> half (gemm_out reads half A)
    #pragma unroll
    for (int ni = 0; ni < 2; ni++) {
        const int col = wn + ni * 8 + 2 * tk;   // even
        const int r0 = m0 + wm + gid;
        const int r1 = r0 + 8;
        if (r0 < S_)
            *(uint32_t*)(g_ctxh + ((size_t)(b * S_ + r0)) * D_ + h * HD_ + col) =
                packh2(cacc[ni][0], cacc[ni][1]);
        if (r1 < S_)
            *(uint32_t*)(g_ctxh + ((size_t)(b * S_ + r1)) * D_ + h * HD_ + col) =
                packh2(cacc[ni][2], cacc[ni][3]);
    }
}

// ---------------------------------------------------------------------------
// Contribution: softmax over q of g_contrib[bh, :]
// ---------------------------------------------------------------------------
__global__ __launch_bounds__(256) void contrib_kernel(float* __restrict__ out)
{
    const int bh = blockIdx.x;
    const float* src = g_contrib + (size_t)bh * S_;
    __shared__ float red[8];
    const int tid = threadIdx.x;

    float m = -3.4e38f;
    for (int i = tid; i < S_; i += 256) m = fmaxf(m, src[i]);
    #pragma unroll
    for (int o = 16; o; o >>= 1) m = fmaxf(m, __shfl_xor_sync(0xffffffffu, m, o));
    if ((tid & 31) == 0) red[tid >> 5] = m;
    __syncthreads();
    if (tid == 0) {
        float mm = red[0];
        #pragma unroll
        for (int w = 1; w < 8; w++) mm = fmaxf(mm, red[w]);
        red[0] = mm;
    }
    __syncthreads();
    m = red[0];
    __syncthreads();

    float s = 0.f;
    for (int i = tid; i < S_; i += 256) s += expf(src[i] - m);
    #pragma unroll
    for (int o = 16; o; o >>= 1) s += __shfl_xor_sync(0xffffffffu, s, o);
    if ((tid & 31) == 0) red[tid >> 5] = s;
    __syncthreads();
    if (tid == 0) {
        float ss = 0.f;
        #pragma unroll
        for (int w = 0; w < 8; w++) ss += red[w];
        red[0] = ss;
    }
    __syncthreads();
    const float inv = 1.0f / red[0];
    for (int i = tid; i < S_; i += 256)
        out[(size_t)bh * S_ + i] = expf(src[i] - m) * inv;
}

// ---------------------------------------------------------------------------
// Launch
// ---------------------------------------------------------------------------
extern "C" void kernel_launch(void* const* d_in, const int* in_sizes, int n_in,
                              void* d_out, int out_size)
{
    const float* hs = (const float*)d_in[0];
    const int*  mask = (const int*) d_in[1];
    const float* Wq = (const float*)d_in[2];
    const float* bq = (const float*)d_in[3];
    const float* Wk = (const float*)d_in[4];
    const float* bk = (const float*)d_in[5];
    const float* Wv = (const float*)d_in[6];
    const float* bv = (const float*)d_in[7];
    const float* Wo = (const float*)d_in[8];
    const float* bo = (const float*)d_in[9];

    float* out     = (float*)d_out;
    float* att_out = out;                                       // [B,S,D]
    float* probs   = out + (size_t)M_ * D_;                     // [B,H,S,S]
    float* contrib = probs + (size_t)BH_ * S_ * S_;             // [B,H,S]

    const int smem_bytes = (QT * PSTR + QT * QSTR + 64 * VSTR) * 4;
    cudaFuncSetAttribute(fused_attn,
        cudaFuncAttributeMaxDynamicSharedMemorySize, smem_bytes);

    // resolve device-global addresses for conversion targets
    __half *xh, *wq, *wk, *wv, *wo;
    cudaGetSymbolAddress((void**)&xh, g_xh);
    cudaGetSymbolAddress((void**)&wq, g_wq);
    cudaGetSymbolAddress((void**)&wk, g_wk);
    cudaGetSymbolAddress((void**)&wv, g_wv);
    cudaGetSymbolAddress((void**)&wo, g_wo);

    // operand conversions (f32 -> f16)
    const int nx4 = (M_ * D_) / 4;       // 1,923,072
    const int nw4 = (D_ * D_) / 4;       // 147,456
    f2h4<<<(nx4 + 255) / 256, 256>>>(hs, xh, nx4);
    f2h4<<<(nw4 + 255) / 256, 256>>>(Wq, wq, nw4);
    f2h4<<<(nw4 + 255) / 256, 256>>>(Wk, wk, nw4);
    f2h4<<<(nw4 + 255) / 256, 256>>>(Wv, wv, nw4);
    f2h4<<<(nw4 + 255) / 256, 256>>>(Wo, wo, nw4);

    gemm_qkv<<<dim3(79, 18), 256>>>(bq, bk, bv);
    fused_attn<<<dim3(20, 192), 256, smem_bytes>>>(probs, mask);
    contrib_kernel<<<BH_, 256>>>(contrib);
    gemm_out<<<dim3(79, 6), 256>>>(bo, att_out);
}

// round 11
// speedup vs baseline: 1.2482x; 1.0828x over previous
#include <cuda_runtime.h>
#include <cuda_fp16.h>
#include <cstdint>

// Problem constants
#define B_   16
#define S_   626
#define D_   768
#define H_   12
#define HD_  64
#define M_   (B_*S_)          // 10016
#define BH_  (B_*H_)          // 192
#define SM1_ (S_-1)           // 625
#define PSTR 644              // P row stride (floats)
#define QSH  72               // Qh/Kh half-tile row stride (halves)
#define VSTR 72               // V tile row stride (floats)
#define QT   32               // q-tile rows in fused_attn
#define AST  24               // proj A tile k-stride (halves)
#define BST  136              // proj B tile n-stride (halves)

// Scratch (device globals; no cudaMalloc allowed)
__device__ __half g_qh[BH_*(size_t)S_*HD_];     // q as half [b,h,s,hd]
__device__ __half g_kh[BH_*(size_t)S_*HD_];     // k as half
__device__ float  g_v [BH_*(size_t)S_*HD_];     // v f32 (tf32 ctx path)
__device__ __half g_ctxh[(size_t)M_*D_];        // ctx as half
__device__ __half g_xh[(size_t)M_*D_];          // hidden_states as half
__device__ __half g_wq[D_*D_], g_wk[D_*D_], g_wv[D_*D_], g_wo[D_*D_];
__device__ float  g_contrib[BH_*S_];            // fixed scores col 0

// ---------------------------------------------------------------------------
// helpers
// ---------------------------------------------------------------------------
__device__ __forceinline__ uint32_t f2t(float x) {
    uint32_t r;
    asm("cvt.rna.tf32.f32 %0, %1;" : "=r"(r) : "f"(x));
    return r;
}

__device__ __forceinline__ void mma_tf32(float c[4],
    uint32_t a0, uint32_t a1, uint32_t a2, uint32_t a3,
    uint32_t b0, uint32_t b1)
{
    asm volatile(
        "mma.sync.aligned.m16n8k8.row.col.f32.tf32.tf32.f32 "
        "{%0,%1,%2,%3}, {%4,%5,%6,%7}, {%8,%9}, {%0,%1,%2,%3};"
        : "+f"(c[0]), "+f"(c[1]), "+f"(c[2]), "+f"(c[3])
        : "r"(a0), "r"(a1), "r"(a2), "r"(a3), "r"(b0), "r"(b1));
}

__device__ __forceinline__ void hmma(float c[4],
    uint32_t a0, uint32_t a1, uint32_t a2, uint32_t a3,
    uint32_t b0, uint32_t b1)
{
    asm volatile(
        "mma.sync.aligned.m16n8k16.row.col.f32.f16.f16.f32 "
        "{%0,%1,%2,%3}, {%4,%5,%6,%7}, {%8,%9}, {%0,%1,%2,%3};"
        : "+f"(c[0]), "+f"(c[1]), "+f"(c[2]), "+f"(c[3])
        : "r"(a0), "r"(a1), "r"(a2), "r"(a3), "r"(b0), "r"(b1));
}

__device__ __forceinline__ void ldsm_x4(
    uint32_t& r0, uint32_t& r1, uint32_t& r2, uint32_t& r3, const void* p)
{
    uint32_t a = (uint32_t)__cvta_generic_to_shared(p);
    asm volatile("ldmatrix.sync.aligned.m8n8.x4.shared.b16 {%0,%1,%2,%3}, [%4];"
        : "=r"(r0), "=r"(r1), "=r"(r2), "=r"(r3) : "r"(a));
}

__device__ __forceinline__ void ldsm_x4_t(
    uint32_t& r0, uint32_t& r1, uint32_t& r2, uint32_t& r3, const void* p)
{
    uint32_t a = (uint32_t)__cvta_generic_to_shared(p);
    asm volatile("ldmatrix.sync.aligned.m8n8.x4.trans.shared.b16 {%0,%1,%2,%3}, [%4];"
        : "=r"(r0), "=r"(r1), "=r"(r2), "=r"(r3) : "r"(a));
}

__device__ __forceinline__ uint2 pack4h(float4 v) {
    uint2 u;
    __half2 h;
    h = __floats2half2_rn(v.x, v.y); u.x = *(uint32_t*)&h;
    h = __floats2half2_rn(v.z, v.w); u.y = *(uint32_t*)&h;
    return u;
}

__device__ __forceinline__ uint32_t packh2(float a, float b) {
    __half2 h = __floats2half2_rn(a, b);
    return *(uint32_t*)&h;
}

// ---------------------------------------------------------------------------
// f32 -> f16 bulk conversion (vectorized, grid-stride)
// ---------------------------------------------------------------------------
__global__ __launch_bounds__(256) void f2h4(
    const float* __restrict__ src, __half* __restrict__ dst, int n4)
{
    for (int i = blockIdx.x * 256 + threadIdx.x; i < n4; i += gridDim.x * 256) {
        float4 v = ((const float4*)src)[i];
        ((uint2*)dst)[i] = pack4h(v);
    }
}

// ---------------------------------------------------------------------------
// Projection GEMM core (fp16 m16n8k16 + ldmatrix, half gmem operands,
// 1 sync/iter, reg double buffer). Block 128x128, BK=16, warp tile 64x32.
// QKV epilogue: half output to dsth (q,k) or f32 to dstf (v); out-proj: f32.
// ---------------------------------------------------------------------------
template <bool QKV>
__device__ __forceinline__ void gemm_core(
    const __half* __restrict__ Asrc, const __half* __restrict__ W,
    const float* __restrict__ bias, float* __restrict__ dstf,
    __half* __restrict__ dsth,
    int m0, int n0,
    __half (*As)[128][AST], __half (*Bs)[16][BST])
{
    const int tid = threadIdx.x;
    const int wid = tid >> 5, lane = tid & 31;
    const int gid = lane >> 2, tk = lane & 3;
    const int wm = (wid & 1) * 64;
    const int wn = (wid >> 1) * 32;
    const int l15 = lane & 15, lhi = (lane >> 4) * 8;

    const int arow = tid >> 1, ak8 = (tid & 1) * 8;
    const int bkr  = tid >> 4, bn8 = (tid & 15) * 8;
    const bool aval = (m0 + arow < M_);

    float acc[4][4][4];
    #pragma unroll
    for (int mi = 0; mi < 4; mi++)
        #pragma unroll
        for (int ni = 0; ni < 4; ni++)
            #pragma unroll
            for (int r = 0; r < 4; r++) acc[mi][ni][r] = 0.f;

    const uint4 z4 = make_uint4(0u, 0u, 0u, 0u);

    {
        uint4 va = z4;
        if (aval) va = *(const uint4*)(Asrc + (size_t)(m0 + arow) * D_ + ak8);
        uint4 vb = *(const uint4*)(W + (size_t)bkr * D_ + n0 + bn8);
        *(uint4*)&As[0][arow][ak8] = va;
        *(uint4*)&Bs[0][bkr][bn8]  = vb;
    }
    __syncthreads();

    const int NK = D_ / 16;   // 48
    for (int kt = 0; kt < NK; kt++) {
        const int cur = kt & 1;
        const bool pf = (kt + 1 < NK);
        uint4 va = z4, vb = z4;
        if (pf) {
            const int k1 = (kt + 1) * 16;
            if (aval) va = *(const uint4*)(Asrc + (size_t)(m0 + arow) * D_ + k1 + ak8);
            vb = *(const uint4*)(W + (size_t)(k1 + bkr) * D_ + n0 + bn8);
        }

        uint32_t af[4][4];
        #pragma unroll
        for (int mi = 0; mi < 4; mi++)
            ldsm_x4(af[mi][0], af[mi][1], af[mi][2], af[mi][3],
                    &As[cur][wm + mi * 16 + l15][lhi]);
        uint32_t bf[8];
        ldsm_x4_t(bf[0], bf[1], bf[2], bf[3], &Bs[cur][l15][wn + lhi]);
        ldsm_x4_t(bf[4], bf[5], bf[6], bf[7], &Bs[cur][l15][wn + 16 + lhi]);

        #pragma unroll
        for (int mi = 0; mi < 4; mi++) {
            hmma(acc[mi][0], af[mi][0], af[mi][1], af[mi][2], af[mi][3], bf[0], bf[1]);
            hmma(acc[mi][1], af[mi][0], af[mi][1], af[mi][2], af[mi][3], bf[2], bf[3]);
            hmma(acc[mi][2], af[mi][0], af[mi][1], af[mi][2], af[mi][3], bf[4], bf[5]);
            hmma(acc[mi][3], af[mi][0], af[mi][1], af[mi][2], af[mi][3], bf[6], bf[7]);
        }

        if (pf) {
            *(uint4*)&As[cur ^ 1][arow][ak8] = va;
            *(uint4*)&Bs[cur ^ 1][bkr][bn8]  = vb;
        }
        __syncthreads();
    }

    #pragma unroll
    for (int mi = 0; mi < 4; mi++) {
        #pragma unroll
        for (int ni = 0; ni < 4; ni++) {
            const int col = n0 + wn + ni * 8 + 2 * tk;
            const float b0v = bias[col], b1v = bias[col + 1];
            const int r0 = m0 + wm + mi * 16 + gid;
            const int r1 = r0 + 8;
            if (QKV) {
                const int h = col >> 6, hd = col & 63;
                if (r0 < M_) {
                    const int b = r0 / S_, s = r0 - b * S_;
                    const size_t off = (((size_t)(b * H_ + h)) * S_ + s) * HD_ + hd;
                    if (dsth) *(uint32_t*)(dsth + off) =
                        packh2(acc[mi][ni][0] + b0v, acc[mi][ni][1] + b1v);
                    else *(float2*)(dstf + off) =
                        make_float2(acc[mi][ni][0] + b0v, acc[mi][ni][1] + b1v);
                }
                if (r1 < M_) {
                    const int b = r1 / S_, s = r1 - b * S_;
                    const size_t off = (((size_t)(b * H_ + h)) * S_ + s) * HD_ + hd;
                    if (dsth) *(uint32_t*)(dsth + off) =
                        packh2(acc[mi][ni][2] + b0v, acc[mi][ni][3] + b1v);
                    else *(float2*)(dstf + off) =
                        make_float2(acc[mi][ni][2] + b0v, acc[mi][ni][3] + b1v);
                }
            } else {
                if (r0 < M_)
                    *(float2*)(dstf + (size_t)r0 * D_ + col) =
                        make_float2(acc[mi][ni][0] + b0v, acc[mi][ni][1] + b1v);
                if (r1 < M_)
                    *(float2*)(dstf + (size_t)r1 * D_ + col) =
                        make_float2(acc[mi][ni][2] + b0v, acc[mi][ni][3] + b1v);
            }
        }
    }
}

__global__ __launch_bounds__(256, 2) void gemm_qkv(
    const float* __restrict__ bq, const float* __restrict__ bk,
    const float* __restrict__ bv)
{
    __shared__ __align__(16) __half As[2][128][AST];
    __shared__ __align__(16) __half Bs[2][16][BST];
    const int m0  = blockIdx.x * 128;
    const int ng  = blockIdx.y * 128;
    const int mat = ng / D_;
    const int n0  = ng - mat * D_;
    const __half* W   = (mat == 0) ? g_wq : (mat == 1) ? g_wk : g_wv;
    const float* bias = (mat == 0) ? bq : (mat == 1) ? bk : bv;
    __half* dsth = (mat == 0) ? g_qh : (mat == 1) ? g_kh : (__half*)nullptr;
    float*  dstf = (mat == 2) ? g_v : nullptr;
    gemm_core<true>(g_xh, W, bias, dstf, dsth, m0, n0, As, Bs);
}

__global__ __launch_bounds__(256, 2) void gemm_out(
    const float* __restrict__ bias, float* __restrict__ out)
{
    __shared__ __align__(16) __half As[2][128][AST];
    __shared__ __align__(16) __half Bs[2][16][BST];
    gemm_core<false>(g_ctxh, g_wo, bias, out, nullptr,
                     blockIdx.x * 128, blockIdx.y * 128, As, Bs);
}

// ---------------------------------------------------------------------------
// Fused attention, 32-row q tile.
//   scores: fp16 ldmatrix path (Qh [m][k], Kh [n][k], non-trans LDSM)
//   softmax: f32 in P (unchanged, proven)
//   ctx:    tf32 path (P f32, V f32) — R8-proven, untouched
// SMEM: P[32][644] f32 + Qh[32][QSH] half + KV union (Kh half / V f32)
// ---------------------------------------------------------------------------
__global__ __launch_bounds__(256) void fused_attn(
    float* __restrict__ probs, const int* __restrict__ mask)
{
    extern __shared__ float sm[];
    float*  P   = sm;                                   // [QT][PSTR] f32
    __half* Qh  = (__half*)(sm + QT * PSTR);            // [QT][QSH] half
    __half* Kh  = (__half*)(Qh + QT * QSH);             // [64][QSH] half
    float*  Vf  = (float*)Kh;                           // [64][VSTR] f32 (union)

    const int bh  = blockIdx.y;
    const int m0  = blockIdx.x * QT;
    const int tid = threadIdx.x;
    const int wid = tid >> 5, lane = tid & 31;
    const int gid = lane >> 2, tk = lane & 3;
    const int wm  = (wid & 1) * 16;     // 2 warps along m
    const int wn  = (wid >> 1) * 16;    // 4 warps along n
    const int l15 = lane & 15, lhi = (lane >> 4) * 8;
    // B-operand (non-trans LDSM on [n][k]) per-lane tile addressing
    const int brow = (lane & 7) + ((lane & 16) ? 8 : 0);
    const int bko  = (lane & 8) ? 8 : 0;
    const int b   = bh / H_;
    const int h   = bh - b * H_;

    const __half* qb = g_qh + (size_t)bh * S_ * HD_;
    const __half* kb = g_kh + (size_t)bh * S_ * HD_;
    const float*  vb = g_v  + (size_t)bh * S_ * HD_;
    float* pgm = probs + (size_t)bh * S_ * S_;

    // zero pad columns 626..PSTR-1 of P (read by ctx tail chunk)
    for (int i = tid; i < QT * (PSTR - S_); i += 256) {
        const int r = i / (PSTR - S_);
        const int c = S_ + i - r * (PSTR - S_);
        P[r * PSTR + c] = 0.f;
    }

    // load Q tile (QT rows x 64 halves): 512 uint2, 2 per thread
    #pragma unroll
    for (int i = 0; i < 2; i++) {
        const int idx = tid + i * 256;
        const int row = idx >> 4, c4 = (idx & 15) << 2;
        uint2 v = make_uint2(0u, 0u);
        if (m0 + row < S_) v = *(const uint2*)(qb + (size_t)(m0 + row) * HD_ + c4);
        *(uint2*)&Qh[row * QSH + c4] = v;
    }

    // ---- scores phase: P[QT][626] = (Q @ K^T) * 0.125, fp16 LDSM ----
    for (int nc = 0; nc < 10; nc++) {
        const int n0 = nc * 64;
        __syncthreads();
        // K tile fill: 64 rows x 64 halves = 1024 uint2, 4 per thread
        #pragma unroll
        for (int i = 0; i < 4; i++) {
            const int idx = tid + i * 256;
            const int row = idx >> 4, c4 = (idx & 15) << 2;
            uint2 v = make_uint2(0u, 0u);
            if (n0 + row < S_) v = *(const uint2*)(kb + (size_t)(n0 + row) * HD_ + c4);
            *(uint2*)&Kh[row * QSH + c4] = v;
        }
        __syncthreads();

        float acc[2][4];
        #pragma unroll
        for (int ni = 0; ni < 2; ni++)
            #pragma unroll
            for (int r = 0; r < 4; r++) acc[ni][r] = 0.f;

        #pragma unroll
        for (int ks = 0; ks < 64; ks += 16) {
            uint32_t a0, a1, a2, a3;
            ldsm_x4(a0, a1, a2, a3, &Qh[(wm + l15) * QSH + ks + lhi]);
            uint32_t b0, b1, b2, b3;
            ldsm_x4(b0, b1, b2, b3, &Kh[(wn + brow) * QSH + ks + bko]);
            hmma(acc[0], a0, a1, a2, a3, b0, b1);
            hmma(acc[1], a0, a1, a2, a3, b2, b3);
        }

        #pragma unroll
        for (int ni = 0; ni < 2; ni++) {
            const int col = n0 + wn + ni * 8 + 2 * tk;   // even
            if (col < S_) {
                *(float2*)&P[(wm + gid    ) * PSTR + col] =
                    make_float2(acc[ni][0] * 0.125f, acc[ni][1] * 0.125f);
                *(float2*)&P[(wm + gid + 8) * PSTR + col] =
                    make_float2(acc[ni][2] * 0.125f, acc[ni][3] * 0.125f);
            }
        }
    }
    __syncthreads();

    // ---- softmax phase (f32): warp w owns rows w*4..w*4+3 ----
    for (int r = wid * 4; r < wid * 4 + 4; r++) {
        const int q = m0 + r;
        if (q >= S_) break;
        float* row = P + r * PSTR;

        float mx = -3.4e38f;
        for (int i = lane; i < S_; i += 32) mx = fmaxf(mx, row[i]);
        #pragma unroll
        for (int o = 16; o; o >>= 1) mx = fmaxf(mx, __shfl_xor_sync(0xffffffffu, mx, o));

        if (q == 0) {
            const float add = mx * 0.25f;
            for (int i = lane; i < S_; i += 32) {
                const int mk = (i == 0) ? 0 : mask[b * SM1_ + i - 1];
                if (mk == 0) row[i] += add;
            }
            __syncwarp();
            mx = -3.4e38f;
            for (int i = lane; i < S_; i += 32) mx = fmaxf(mx, row[i]);
            #pragma unroll
            for (int o = 16; o; o >>= 1) mx = fmaxf(mx, __shfl_xor_sync(0xffffffffu, mx, o));
        }

        if (lane == 0) g_contrib[(size_t)bh * S_ + q] = row[0];

        float s = 0.f;
        for (int i = lane; i < S_; i += 32) {
            const float e = expf(row[i] - mx);
            row[i] = e;
            s += e;
        }
        #pragma unroll
        for (int o = 16; o; o >>= 1) s += __shfl_xor_sync(0xffffffffu, s, o);
        const float inv = 1.0f / s;

        float* prow = pgm + (size_t)q * S_;
        for (int i = lane; i < S_; i += 32) {
            const float p = row[i] * inv;
            row[i] = p;
            prow[i] = p;
        }
    }
    __syncthreads();

    // ---- ctx phase: tf32 (R8-proven, unchanged) ----
    float cacc[2][4];
    #pragma unroll
    for (int ni = 0; ni < 2; ni++)
        #pragma unroll
        for (int r = 0; r < 4; r++) cacc[ni][r] = 0.f;

    for (int kc = 0; kc < 10; kc++) {
        const int k0 = kc * 64;
        __syncthreads();
        #pragma unroll
        for (int i = 0; i < 4; i++) {
            const int idx = tid + i * 256;
            const int row = idx >> 4, c4 = (idx & 15) << 2;
            float4 v = make_float4(0.f, 0.f, 0.f, 0.f);
            if (k0 + row < S_) v = *(const float4*)(vb + (size_t)(k0 + row) * HD_ + c4);
            uint4 t;
            t.x = f2t(v.x); t.y = f2t(v.y); t.z = f2t(v.z); t.w = f2t(v.w);
            *(uint4*)&((uint32_t*)Vf)[row * VSTR + c4] = t;
        }
        __syncthreads();

        #pragma unroll
        for (int ks = 0; ks < 64; ks += 8) {
            const uint32_t a0 = f2t(P[(wm + gid    ) * PSTR + k0 + ks + tk]);
            const uint32_t a1 = f2t(P[(wm + gid + 8) * PSTR + k0 + ks + tk]);
            const uint32_t a2 = f2t(P[(wm + gid    ) * PSTR + k0 + ks + tk + 4]);
            const uint32_t a3 = f2t(P[(wm + gid + 8) * PSTR + k0 + ks + tk + 4]);
            #pragma unroll
            for (int ni = 0; ni < 2; ni++) {
                mma_tf32(cacc[ni], a0, a1, a2, a3,
                         ((uint32_t*)Vf)[(ks + tk    ) * VSTR + wn + ni * 8 + gid],
                         ((uint32_t*)Vf)[(ks + tk + 4) * VSTR + wn + ni * 8 + gid]);
            }
        }
    }

    // ctx epilogue -> half (gemm_out reads half A)
    #pragma unroll
    for (int ni = 0; ni < 2; ni++) {
        const int col = wn + ni * 8 + 2 * tk;   // even
        const int r0 = m0 + wm + gid;
        const int r1 = r0 + 8;
        if (r0 < S_)
            *(uint32_t*)(g_ctxh + ((size_t)(b * S_ + r0)) * D_ + h * HD_ + col) =
                packh2(cacc[ni][0], cacc[ni][1]);
        if (r1 < S_)
            *(uint32_t*)(g_ctxh + ((size_t)(b * S_ + r1)) * D_ + h * HD_ + col) =
                packh2(cacc[ni][2], cacc[ni][3]);
    }
}

// ---------------------------------------------------------------------------
// Contribution: softmax over q of g_contrib[bh, :]
// ---------------------------------------------------------------------------
__global__ __launch_bounds__(256) void contrib_kernel(float* __restrict__ out)
{
    const int bh = blockIdx.x;
    const float* src = g_contrib + (size_t)bh * S_;
    __shared__ float red[8];
    const int tid = threadIdx.x;

    float m = -3.4e38f;
    for (int i = tid; i < S_; i += 256) m = fmaxf(m, src[i]);
    #pragma unroll
    for (int o = 16; o; o >>= 1) m = fmaxf(m, __shfl_xor_sync(0xffffffffu, m, o));
    if ((tid & 31) == 0) red[tid >> 5] = m;
    __syncthreads();
    if (tid == 0) {
        float mm = red[0];
        #pragma unroll
        for (int w = 1; w < 8; w++) mm = fmaxf(mm, red[w]);
        red[0] = mm;
    }
    __syncthreads();
    m = red[0];
    __syncthreads();

    float s = 0.f;
    for (int i = tid; i < S_; i += 256) s += expf(src[i] - m);
    #pragma unroll
    for (int o = 16; o; o >>= 1) s += __shfl_xor_sync(0xffffffffu, s, o);
    if ((tid & 31) == 0) red[tid >> 5] = s;
    __syncthreads();
    if (tid == 0) {
        float ss = 0.f;
        #pragma unroll
        for (int w = 0; w < 8; w++) ss += red[w];
        red[0] = ss;
    }
    __syncthreads();
    const float inv = 1.0f / red[0];
    for (int i = tid; i < S_; i += 256)
        out[(size_t)bh * S_ + i] = expf(src[i] - m) * inv;
}

// ---------------------------------------------------------------------------
// Launch
// ---------------------------------------------------------------------------
extern "C" void kernel_launch(void* const* d_in, const int* in_sizes, int n_in,
                              void* d_out, int out_size)
{
    const float* hs = (const float*)d_in[0];
    const int*  mask = (const int*) d_in[1];
    const float* Wq = (const float*)d_in[2];
    const float* bq = (const float*)d_in[3];
    const float* Wk = (const float*)d_in[4];
    const float* bk = (const float*)d_in[5];
    const float* Wv = (const float*)d_in[6];
    const float* bv = (const float*)d_in[7];
    const float* Wo = (const float*)d_in[8];
    const float* bo = (const float*)d_in[9];

    float* out     = (float*)d_out;
    float* att_out = out;                                       // [B,S,D]
    float* probs   = out + (size_t)M_ * D_;                     // [B,H,S,S]
    float* contrib = probs + (size_t)BH_ * S_ * S_;             // [B,H,S]

    // SMEM: P f32 + Qh half + KV union (Kh half 9216B vs Vf f32 18432B -> 18432)
    const int smem_bytes = QT * PSTR * 4 + QT * QSH * 2 + 64 * VSTR * 4;
    cudaFuncSetAttribute(fused_attn,
        cudaFuncAttributeMaxDynamicSharedMemorySize, smem_bytes);

    __half *xh, *wq, *wk, *wv, *wo;
    cudaGetSymbolAddress((void**)&xh, g_xh);
    cudaGetSymbolAddress((void**)&wq, g_wq);
    cudaGetSymbolAddress((void**)&wk, g_wk);
    cudaGetSymbolAddress((void**)&wv, g_wv);
    cudaGetSymbolAddress((void**)&wo, g_wo);

    const int nx4 = (M_ * D_) / 4;
    const int nw4 = (D_ * D_) / 4;
    f2h4<<<(nx4 + 255) / 256, 256>>>(hs, xh, nx4);
    f2h4<<<(nw4 + 255) / 256, 256>>>(Wq, wq, nw4);
    f2h4<<<(nw4 + 255) / 256, 256>>>(Wk, wk, nw4);
    f2h4<<<(nw4 + 255) / 256, 256>>>(Wv, wv, nw4);
    f2h4<<<(nw4 + 255) / 256, 256>>>(Wo, wo, nw4);

    gemm_qkv<<<dim3(79, 18), 256>>>(bq, bk, bv);
    fused_attn<<<dim3(20, 192), 256, smem_bytes>>>(probs, mask);
    contrib_kernel<<<BH_, 256>>>(contrib);
    gemm_out<<<dim3(79, 6), 256>>>(bo, att_out);
}

// round 12
// speedup vs baseline: 1.4853x; 1.1900x over previous
#include <cuda_runtime.h>
#include <cuda_fp16.h>
#include <cstdint>

// Problem constants
#define B_   16
#define S_   626
#define D_   768
#define H_   12
#define HD_  64
#define M_   (B_*S_)          // 10016
#define BH_  (B_*H_)          // 192
#define SM1_ (S_-1)           // 625
#define PSTR 648              // P row stride (floats), 648 % 32 == 8 -> optimal float2 LDS
#define QSH  72               // Qh/Kh/Vh half-tile row stride (halves)
#define QT   32               // q-tile rows in fused_attn
#define AST  24               // proj A tile k-stride (halves)
#define BST  136              // proj B tile n-stride (halves)

// Scratch (device globals; no cudaMalloc allowed)
__device__ __half g_qh[BH_*(size_t)S_*HD_];     // q as half [b,h,s,hd]
__device__ __half g_kh[BH_*(size_t)S_*HD_];     // k as half
__device__ __half g_vh[BH_*(size_t)S_*HD_];     // v as half
__device__ __half g_ctxh[(size_t)M_*D_];        // ctx as half
__device__ __half g_xh[(size_t)M_*D_];          // hidden_states as half
__device__ __half g_wq[D_*D_], g_wk[D_*D_], g_wv[D_*D_], g_wo[D_*D_];
__device__ float  g_contrib[BH_*S_];            // fixed scores col 0

// ---------------------------------------------------------------------------
// helpers
// ---------------------------------------------------------------------------
__device__ __forceinline__ void hmma(float c[4],
    uint32_t a0, uint32_t a1, uint32_t a2, uint32_t a3,
    uint32_t b0, uint32_t b1)
{
    asm volatile(
        "mma.sync.aligned.m16n8k16.row.col.f32.f16.f16.f32 "
        "{%0,%1,%2,%3}, {%4,%5,%6,%7}, {%8,%9}, {%0,%1,%2,%3};"
        : "+f"(c[0]), "+f"(c[1]), "+f"(c[2]), "+f"(c[3])
        : "r"(a0), "r"(a1), "r"(a2), "r"(a3), "r"(b0), "r"(b1));
}

__device__ __forceinline__ void ldsm_x4(
    uint32_t& r0, uint32_t& r1, uint32_t& r2, uint32_t& r3, const void* p)
{
    uint32_t a = (uint32_t)__cvta_generic_to_shared(p);
    asm volatile("ldmatrix.sync.aligned.m8n8.x4.shared.b16 {%0,%1,%2,%3}, [%4];"
        : "=r"(r0), "=r"(r1), "=r"(r2), "=r"(r3) : "r"(a));
}

__device__ __forceinline__ void ldsm_x4_t(
    uint32_t& r0, uint32_t& r1, uint32_t& r2, uint32_t& r3, const void* p)
{
    uint32_t a = (uint32_t)__cvta_generic_to_shared(p);
    asm volatile("ldmatrix.sync.aligned.m8n8.x4.trans.shared.b16 {%0,%1,%2,%3}, [%4];"
        : "=r"(r0), "=r"(r1), "=r"(r2), "=r"(r3) : "r"(a));
}

__device__ __forceinline__ uint2 pack4h(float4 v) {
    uint2 u;
    __half2 h;
    h = __floats2half2_rn(v.x, v.y); u.x = *(uint32_t*)&h;
    h = __floats2half2_rn(v.z, v.w); u.y = *(uint32_t*)&h;
    return u;
}

__device__ __forceinline__ uint32_t packh2(float a, float b) {
    __half2 h = __floats2half2_rn(a, b);
    return *(uint32_t*)&h;
}

// ---------------------------------------------------------------------------
// f32 -> f16 bulk conversion (vectorized, grid-stride)
// ---------------------------------------------------------------------------
__global__ __launch_bounds__(256) void f2h4(
    const float* __restrict__ src, __half* __restrict__ dst, int n4)
{
    for (int i = blockIdx.x * 256 + threadIdx.x; i < n4; i += gridDim.x * 256) {
        float4 v = ((const float4*)src)[i];
        ((uint2*)dst)[i] = pack4h(v);
    }
}

// ---------------------------------------------------------------------------
// Projection GEMM core (fp16 m16n8k16 + ldmatrix, half gmem operands,
// 1 sync/iter, reg double buffer). Block 128x128, BK=16, warp tile 64x32.
// QKV epilogue: half output (scattered); out-proj: f32 rows.
// ---------------------------------------------------------------------------
template <bool QKV>
__device__ __forceinline__ void gemm_core(
    const __half* __restrict__ Asrc, const __half* __restrict__ W,
    const float* __restrict__ bias, float* __restrict__ dstf,
    __half* __restrict__ dsth,
    int m0, int n0,
    __half (*As)[128][AST], __half (*Bs)[16][BST])
{
    const int tid = threadIdx.x;
    const int wid = tid >> 5, lane = tid & 31;
    const int gid = lane >> 2, tk = lane & 3;
    const int wm = (wid & 1) * 64;
    const int wn = (wid >> 1) * 32;
    const int l15 = lane & 15, lhi = (lane >> 4) * 8;

    const int arow = tid >> 1, ak8 = (tid & 1) * 8;
    const int bkr  = tid >> 4, bn8 = (tid & 15) * 8;
    const bool aval = (m0 + arow < M_);

    float acc[4][4][4];
    #pragma unroll
    for (int mi = 0; mi < 4; mi++)
        #pragma unroll
        for (int ni = 0; ni < 4; ni++)
            #pragma unroll
            for (int r = 0; r < 4; r++) acc[mi][ni][r] = 0.f;

    const uint4 z4 = make_uint4(0u, 0u, 0u, 0u);

    {
        uint4 va = z4;
        if (aval) va = *(const uint4*)(Asrc + (size_t)(m0 + arow) * D_ + ak8);
        uint4 vb = *(const uint4*)(W + (size_t)bkr * D_ + n0 + bn8);
        *(uint4*)&As[0][arow][ak8] = va;
        *(uint4*)&Bs[0][bkr][bn8]  = vb;
    }
    __syncthreads();

    const int NK = D_ / 16;   // 48
    for (int kt = 0; kt < NK; kt++) {
        const int cur = kt & 1;
        const bool pf = (kt + 1 < NK);
        uint4 va = z4, vb = z4;
        if (pf) {
            const int k1 = (kt + 1) * 16;
            if (aval) va = *(const uint4*)(Asrc + (size_t)(m0 + arow) * D_ + k1 + ak8);
            vb = *(const uint4*)(W + (size_t)(k1 + bkr) * D_ + n0 + bn8);
        }

        uint32_t af[4][4];
        #pragma unroll
        for (int mi = 0; mi < 4; mi++)
            ldsm_x4(af[mi][0], af[mi][1], af[mi][2], af[mi][3],
                    &As[cur][wm + mi * 16 + l15][lhi]);
        uint32_t bf[8];
        ldsm_x4_t(bf[0], bf[1], bf[2], bf[3], &Bs[cur][l15][wn + lhi]);
        ldsm_x4_t(bf[4], bf[5], bf[6], bf[7], &Bs[cur][l15][wn + 16 + lhi]);

        #pragma unroll
        for (int mi = 0; mi < 4; mi++) {
            hmma(acc[mi][0], af[mi][0], af[mi][1], af[mi][2], af[mi][3], bf[0], bf[1]);
            hmma(acc[mi][1], af[mi][0], af[mi][1], af[mi][2], af[mi][3], bf[2], bf[3]);
            hmma(acc[mi][2], af[mi][0], af[mi][1], af[mi][2], af[mi][3], bf[4], bf[5]);
            hmma(acc[mi][3], af[mi][0], af[mi][1], af[mi][2], af[mi][3], bf[6], bf[7]);
        }

        if (pf) {
            *(uint4*)&As[cur ^ 1][arow][ak8] = va;
            *(uint4*)&Bs[cur ^ 1][bkr][bn8]  = vb;
        }
        __syncthreads();
    }

    #pragma unroll
    for (int mi = 0; mi < 4; mi++) {
        #pragma unroll
        for (int ni = 0; ni < 4; ni++) {
            const int col = n0 + wn + ni * 8 + 2 * tk;
            const float b0v = bias[col], b1v = bias[col + 1];
            const int r0 = m0 + wm + mi * 16 + gid;
            const int r1 = r0 + 8;
            if (QKV) {
                const int h = col >> 6, hd = col & 63;
                if (r0 < M_) {
                    const int b = r0 / S_, s = r0 - b * S_;
                    *(uint32_t*)(dsth + (((size_t)(b * H_ + h)) * S_ + s) * HD_ + hd) =
                        packh2(acc[mi][ni][0] + b0v, acc[mi][ni][1] + b1v);
                }
                if (r1 < M_) {
                    const int b = r1 / S_, s = r1 - b * S_;
                    *(uint32_t*)(dsth + (((size_t)(b * H_ + h)) * S_ + s) * HD_ + hd) =
                        packh2(acc[mi][ni][2] + b0v, acc[mi][ni][3] + b1v);
                }
            } else {
                if (r0 < M_)
                    *(float2*)(dstf + (size_t)r0 * D_ + col) =
                        make_float2(acc[mi][ni][0] + b0v, acc[mi][ni][1] + b1v);
                if (r1 < M_)
                    *(float2*)(dstf + (size_t)r1 * D_ + col) =
                        make_float2(acc[mi][ni][2] + b0v, acc[mi][ni][3] + b1v);
            }
        }
    }
}

__global__ __launch_bounds__(256, 2) void gemm_qkv(
    const float* __restrict__ bq, const float* __restrict__ bk,
    const float* __restrict__ bv)
{
    __shared__ __align__(16) __half As[2][128][AST];
    __shared__ __align__(16) __half Bs[2][16][BST];
    const int m0  = blockIdx.x * 128;
    const int ng  = blockIdx.y * 128;
    const int mat = ng / D_;
    const int n0  = ng - mat * D_;
    const __half* W   = (mat == 0) ? g_wq : (mat == 1) ? g_wk : g_wv;
    const float* bias = (mat == 0) ? bq : (mat == 1) ? bk : bv;
    __half* dsth = (mat == 0) ? g_qh : (mat == 1) ? g_kh : g_vh;
    gemm_core<true>(g_xh, W, bias, nullptr, dsth, m0, n0, As, Bs);
}

__global__ __launch_bounds__(256, 2) void gemm_out(
    const float* __restrict__ bias, float* __restrict__ out)
{
    __shared__ __align__(16) __half As[2][128][AST];
    __shared__ __align__(16) __half Bs[2][16][BST];
    gemm_core<false>(g_ctxh, g_wo, bias, out, nullptr,
                     blockIdx.x * 128, blockIdx.y * 128, As, Bs);
}

// ---------------------------------------------------------------------------
// Fused attention, 32-row q tile, fp16 MMA both phases, 128-wide chunks.
//   scores: Qh [m][k] x Kh [n][k] (non-trans LDSM), 5 chunks of 128 cols
//   softmax: f32 in P (proven)
//   ctx:    P (float2 LDS at stride 648 -> bank-optimal) x Vh [k][n] trans-LDSM
// SMEM: P[32][648] f32 + Qh[32][QSH] half + KVh[128][QSH] half  (~103.5 KB)
// ---------------------------------------------------------------------------
__global__ __launch_bounds__(256) void fused_attn(
    float* __restrict__ probs, const int* __restrict__ mask)
{
    extern __shared__ float sm[];
    float*  P   = sm;                                   // [QT][PSTR] f32
    __half* Qh  = (__half*)(sm + QT * PSTR);            // [QT][QSH]
    __half* KVh = Qh + QT * QSH;                        // [128][QSH]

    const int bh  = blockIdx.y;
    const int m0  = blockIdx.x * QT;
    const int tid = threadIdx.x;
    const int wid = tid >> 5, lane = tid & 31;
    const int gid = lane >> 2, tk = lane & 3;
    const int wm  = (wid & 1) * 16;      // 2 warps along m (16 rows)
    const int wns = (wid >> 1) * 32;     // scores: 4 warps x 32 cols = 128
    const int wnc = (wid >> 1) * 16;     // ctx: 4 warps x 16 cols = 64
    const int l15 = lane & 15, lhi = (lane >> 4) * 8;
    const int brow = (lane & 7) + ((lane & 16) ? 8 : 0);   // non-trans B lane row
    const int bko  = (lane & 8) ? 8 : 0;                    // non-trans B k offset
    const int b   = bh / H_;
    const int h   = bh - b * H_;

    const __half* qb = g_qh + (size_t)bh * S_ * HD_;
    const __half* kb = g_kh + (size_t)bh * S_ * HD_;
    const __half* vb = g_vh + (size_t)bh * S_ * HD_;
    float* pgm = probs + (size_t)bh * S_ * S_;

    // zero pad columns 626..PSTR-1 of P (read by ctx tail chunk)
    for (int i = tid; i < QT * (PSTR - S_); i += 256) {
        const int r = i / (PSTR - S_);
        const int c = S_ + i - r * (PSTR - S_);
        P[r * PSTR + c] = 0.f;
    }

    // load Q tile (QT rows x 64 halves): 512 uint2, 2 per thread
    #pragma unroll
    for (int i = 0; i < 2; i++) {
        const int idx = tid + i * 256;
        const int row = idx >> 4, c4 = (idx & 15) << 2;
        uint2 v = make_uint2(0u, 0u);
        if (m0 + row < S_) v = *(const uint2*)(qb + (size_t)(m0 + row) * HD_ + c4);
        *(uint2*)&Qh[row * QSH + c4] = v;
    }

    // ---- scores phase: 5 chunks of 128 key-columns ----
    for (int nc = 0; nc < 5; nc++) {
        const int n0 = nc * 128;
        __syncthreads();
        // K tile fill: 128 rows x 64 halves = 2048 uint2, 8 per thread
        #pragma unroll
        for (int i = 0; i < 8; i++) {
            const int idx = tid + i * 256;
            const int row = idx >> 4, c4 = (idx & 15) << 2;
            uint2 v = make_uint2(0u, 0u);
            if (n0 + row < S_) v = *(const uint2*)(kb + (size_t)(n0 + row) * HD_ + c4);
            *(uint2*)&KVh[row * QSH + c4] = v;
        }
        __syncthreads();

        float acc[4][4];
        #pragma unroll
        for (int ni = 0; ni < 4; ni++)
            #pragma unroll
            for (int r = 0; r < 4; r++) acc[ni][r] = 0.f;

        #pragma unroll
        for (int ks = 0; ks < 64; ks += 16) {
            uint32_t a0, a1, a2, a3;
            ldsm_x4(a0, a1, a2, a3, &Qh[(wm + l15) * QSH + ks + lhi]);
            #pragma unroll
            for (int nt = 0; nt < 2; nt++) {
                uint32_t b0, b1, b2, b3;
                ldsm_x4(b0, b1, b2, b3,
                        &KVh[(wns + nt * 16 + brow) * QSH + ks + bko]);
                hmma(acc[nt * 2 + 0], a0, a1, a2, a3, b0, b1);
                hmma(acc[nt * 2 + 1], a0, a1, a2, a3, b2, b3);
            }
        }

        #pragma unroll
        for (int ni = 0; ni < 4; ni++) {
            const int col = n0 + wns + ni * 8 + 2 * tk;   // even
            if (col < S_) {
                *(float2*)&P[(wm + gid    ) * PSTR + col] =
                    make_float2(acc[ni][0] * 0.125f, acc[ni][1] * 0.125f);
                *(float2*)&P[(wm + gid + 8) * PSTR + col] =
                    make_float2(acc[ni][2] * 0.125f, acc[ni][3] * 0.125f);
            }
        }
    }
    __syncthreads();

    // ---- softmax phase (f32): warp w owns rows w*4..w*4+3 ----
    for (int r = wid * 4; r < wid * 4 + 4; r++) {
        const int q = m0 + r;
        if (q >= S_) break;
        float* row = P + r * PSTR;

        float mx = -3.4e38f;
        for (int i = lane; i < S_; i += 32) mx = fmaxf(mx, row[i]);
        #pragma unroll
        for (int o = 16; o; o >>= 1) mx = fmaxf(mx, __shfl_xor_sync(0xffffffffu, mx, o));

        if (q == 0) {
            const float add = mx * 0.25f;
            for (int i = lane; i < S_; i += 32) {
                const int mk = (i == 0) ? 0 : mask[b * SM1_ + i - 1];
                if (mk == 0) row[i] += add;
            }
            __syncwarp();
            mx = -3.4e38f;
            for (int i = lane; i < S_; i += 32) mx = fmaxf(mx, row[i]);
            #pragma unroll
            for (int o = 16; o; o >>= 1) mx = fmaxf(mx, __shfl_xor_sync(0xffffffffu, mx, o));
        }

        if (lane == 0) g_contrib[(size_t)bh * S_ + q] = row[0];

        float s = 0.f;
        for (int i = lane; i < S_; i += 32) {
            const float e = expf(row[i] - mx);
            row[i] = e;
            s += e;
        }
        #pragma unroll
        for (int o = 16; o; o >>= 1) s += __shfl_xor_sync(0xffffffffu, s, o);
        const float inv = 1.0f / s;

        float* prow = pgm + (size_t)q * S_;
        for (int i = lane; i < S_; i += 32) {
            const float p = row[i] * inv;
            row[i] = p;
            prow[i] = p;
        }
    }
    __syncthreads();

    // ---- ctx phase: 5 chunks of 128 k-rows, fp16 MMA ----
    float cacc[2][4];
    #pragma unroll
    for (int ni = 0; ni < 2; ni++)
        #pragma unroll
        for (int r = 0; r < 4; r++) cacc[ni][r] = 0.f;

    for (int kc = 0; kc < 5; kc++) {
        const int k0 = kc * 128;
        __syncthreads();
        // V tile fill: 128 rows x 64 halves
        #pragma unroll
        for (int i = 0; i < 8; i++) {
            const int idx = tid + i * 256;
            const int row = idx >> 4, c4 = (idx & 15) << 2;
            uint2 v = make_uint2(0u, 0u);
            if (k0 + row < S_) v = *(const uint2*)(vb + (size_t)(k0 + row) * HD_ + c4);
            *(uint2*)&KVh[row * QSH + c4] = v;
        }
        __syncthreads();

        #pragma unroll
        for (int ks = 0; ks < 128; ks += 16) {
            const float* pr0 = P + (wm + gid    ) * PSTR + k0 + ks + 2 * tk;
            const float* pr1 = P + (wm + gid + 8) * PSTR + k0 + ks + 2 * tk;
            const float2 v0 = *(const float2*)pr0;
            const float2 v1 = *(const float2*)pr1;
            const float2 v2 = *(const float2*)(pr0 + 8);
            const float2 v3 = *(const float2*)(pr1 + 8);
            const uint32_t a0 = packh2(v0.x, v0.y);
            const uint32_t a1 = packh2(v1.x, v1.y);
            const uint32_t a2 = packh2(v2.x, v2.y);
            const uint32_t a3 = packh2(v3.x, v3.y);
            uint32_t b0, b1, b2, b3;
            ldsm_x4_t(b0, b1, b2, b3, &KVh[(ks + l15) * QSH + wnc + lhi]);
            hmma(cacc[0], a0, a1, a2, a3, b0, b1);
            hmma(cacc[1], a0, a1, a2, a3, b2, b3);
        }
    }

    // ctx epilogue -> half (gemm_out reads half A)
    #pragma unroll
    for (int ni = 0; ni < 2; ni++) {
        const int col = wnc + ni * 8 + 2 * tk;   // even, 0..62
        const int r0 = m0 + wm + gid;
        const int r1 = r0 + 8;
        if (r0 < S_)
            *(uint32_t*)(g_ctxh + ((size_t)(b * S_ + r0)) * D_ + h * HD_ + col) =
                packh2(cacc[ni][0], cacc[ni][1]);
        if (r1 < S_)
            *(uint32_t*)(g_ctxh + ((size_t)(b * S_ + r1)) * D_ + h * HD_ + col) =
                packh2(cacc[ni][2], cacc[ni][3]);
    }
}

// ---------------------------------------------------------------------------
// Contribution: softmax over q of g_contrib[bh, :]
// ---------------------------------------------------------------------------
__global__ __launch_bounds__(256) void contrib_kernel(float* __restrict__ out)
{
    const int bh = blockIdx.x;
    const float* src = g_contrib + (size_t)bh * S_;
    __shared__ float red[8];
    const int tid = threadIdx.x;

    float m = -3.4e38f;
    for (int i = tid; i < S_; i += 256) m = fmaxf(m, src[i]);
    #pragma unroll
    for (int o = 16; o; o >>= 1) m = fmaxf(m, __shfl_xor_sync(0xffffffffu, m, o));
    if ((tid & 31) == 0) red[tid >> 5] = m;
    __syncthreads();
    if (tid == 0) {
        float mm = red[0];
        #pragma unroll
        for (int w = 1; w < 8; w++) mm = fmaxf(mm, red[w]);
        red[0] = mm;
    }
    __syncthreads();
    m = red[0];
    __syncthreads();

    float s = 0.f;
    for (int i = tid; i < S_; i += 256) s += expf(src[i] - m);
    #pragma unroll
    for (int o = 16; o; o >>= 1) s += __shfl_xor_sync(0xffffffffu, s, o);
    if ((tid & 31) == 0) red[tid >> 5] = s;
    __syncthreads();
    if (tid == 0) {
        float ss = 0.f;
        #pragma unroll
        for (int w = 0; w < 8; w++) ss += red[w];
        red[0] = ss;
    }
    __syncthreads();
    const float inv = 1.0f / red[0];
    for (int i = tid; i < S_; i += 256)
        out[(size_t)bh * S_ + i] = expf(src[i] - m) * inv;
}

// ---------------------------------------------------------------------------
// Launch
// ---------------------------------------------------------------------------
extern "C" void kernel_launch(void* const* d_in, const int* in_sizes, int n_in,
                              void* d_out, int out_size)
{
    const float* hs = (const float*)d_in[0];
    const int*  mask = (const int*) d_in[1];
    const float* Wq = (const float*)d_in[2];
    const float* bq = (const float*)d_in[3];
    const float* Wk = (const float*)d_in[4];
    const float* bk = (const float*)d_in[5];
    const float* Wv = (const float*)d_in[6];
    const float* bv = (const float*)d_in[7];
    const float* Wo = (const float*)d_in[8];
    const float* bo = (const float*)d_in[9];

    float* out     = (float*)d_out;
    float* att_out = out;                                       // [B,S,D]
    float* probs   = out + (size_t)M_ * D_;                     // [B,H,S,S]
    float* contrib = probs + (size_t)BH_ * S_ * S_;             // [B,H,S]

    // SMEM: P f32 + Qh half + KVh half (128 rows)
    const int smem_bytes = QT * PSTR * 4 + QT * QSH * 2 + 128 * QSH * 2;
    cudaFuncSetAttribute(fused_attn,
        cudaFuncAttributeMaxDynamicSharedMemorySize, smem_bytes);

    __half *xh, *wq, *wk, *wv, *wo;
    cudaGetSymbolAddress((void**)&xh, g_xh);
    cudaGetSymbolAddress((void**)&wq, g_wq);
    cudaGetSymbolAddress((void**)&wk, g_wk);
    cudaGetSymbolAddress((void**)&wv, g_wv);
    cudaGetSymbolAddress((void**)&wo, g_wo);

    const int nx4 = (M_ * D_) / 4;
    const int nw4 = (D_ * D_) / 4;
    f2h4<<<(nx4 + 255) / 256, 256>>>(hs, xh, nx4);
    f2h4<<<(nw4 + 255) / 256, 256>>>(Wq, wq, nw4);
    f2h4<<<(nw4 + 255) / 256, 256>>>(Wk, wk, nw4);
    f2h4<<<(nw4 + 255) / 256, 256>>>(Wv, wv, nw4);
    f2h4<<<(nw4 + 255) / 256, 256>>>(Wo, wo, nw4);

    gemm_qkv<<<dim3(79, 18), 256>>>(bq, bk, bv);
    fused_attn<<<dim3(20, 192), 256, smem_bytes>>>(probs, mask);
    contrib_kernel<<<BH_, 256>>>(contrib);
    gemm_out<<<dim3(79, 6), 256>>>(bo, att_out);
}

// round 13
// speedup vs baseline: 1.4900x; 1.0031x over previous
#include <cuda_runtime.h>
#include <cuda_fp16.h>
#include <cstdint>

// Problem constants
#define B_   16
#define S_   626
#define D_   768
#define H_   12
#define HD_  64
#define M_   (B_*S_)          // 10016
#define BH_  (B_*H_)          // 192
#define SM1_ (S_-1)           // 625
#define PSTR 648              // P row stride (floats), 648 % 32 == 8 -> optimal float2 LDS
#define QSH  72               // Qh/Kh/Vh half-tile row stride (halves)
#define QT   64               // q-tile rows in fused_attn (512 threads, 1 block/SM)
#define AST  24               // proj A tile k-stride (halves)
#define BST  136              // proj B tile n-stride (halves)

// Scratch (device globals; no cudaMalloc allowed)
__device__ __half g_qh[BH_*(size_t)S_*HD_];     // q as half [b,h,s,hd]
__device__ __half g_kh[BH_*(size_t)S_*HD_];     // k as half
__device__ __half g_vh[BH_*(size_t)S_*HD_];     // v as half
__device__ __half g_ctxh[(size_t)M_*D_];        // ctx as half
__device__ __half g_xh[(size_t)M_*D_];          // hidden_states as half
__device__ __half g_wq[D_*D_], g_wk[D_*D_], g_wv[D_*D_], g_wo[D_*D_];
__device__ float  g_contrib[BH_*S_];            // fixed scores col 0

// ---------------------------------------------------------------------------
// helpers
// ---------------------------------------------------------------------------
__device__ __forceinline__ void hmma(float c[4],
    uint32_t a0, uint32_t a1, uint32_t a2, uint32_t a3,
    uint32_t b0, uint32_t b1)
{
    asm volatile(
        "mma.sync.aligned.m16n8k16.row.col.f32.f16.f16.f32 "
        "{%0,%1,%2,%3}, {%4,%5,%6,%7}, {%8,%9}, {%0,%1,%2,%3};"
        : "+f"(c[0]), "+f"(c[1]), "+f"(c[2]), "+f"(c[3])
        : "r"(a0), "r"(a1), "r"(a2), "r"(a3), "r"(b0), "r"(b1));
}

__device__ __forceinline__ void ldsm_x4(
    uint32_t& r0, uint32_t& r1, uint32_t& r2, uint32_t& r3, const void* p)
{
    uint32_t a = (uint32_t)__cvta_generic_to_shared(p);
    asm volatile("ldmatrix.sync.aligned.m8n8.x4.shared.b16 {%0,%1,%2,%3}, [%4];"
        : "=r"(r0), "=r"(r1), "=r"(r2), "=r"(r3) : "r"(a));
}

__device__ __forceinline__ void ldsm_x4_t(
    uint32_t& r0, uint32_t& r1, uint32_t& r2, uint32_t& r3, const void* p)
{
    uint32_t a = (uint32_t)__cvta_generic_to_shared(p);
    asm volatile("ldmatrix.sync.aligned.m8n8.x4.trans.shared.b16 {%0,%1,%2,%3}, [%4];"
        : "=r"(r0), "=r"(r1), "=r"(r2), "=r"(r3) : "r"(a));
}

__device__ __forceinline__ uint2 pack4h(float4 v) {
    uint2 u;
    __half2 h;
    h = __floats2half2_rn(v.x, v.y); u.x = *(uint32_t*)&h;
    h = __floats2half2_rn(v.z, v.w); u.y = *(uint32_t*)&h;
    return u;
}

__device__ __forceinline__ uint32_t packh2(float a, float b) {
    __half2 h = __floats2half2_rn(a, b);
    return *(uint32_t*)&h;
}

// ---------------------------------------------------------------------------
// f32 -> f16 bulk conversions
// ---------------------------------------------------------------------------
__global__ __launch_bounds__(256) void f2h4(
    const float* __restrict__ src, __half* __restrict__ dst, int n4)
{
    for (int i = blockIdx.x * 256 + threadIdx.x; i < n4; i += gridDim.x * 256) {
        float4 v = ((const float4*)src)[i];
        ((uint2*)dst)[i] = pack4h(v);
    }
}

// all 4 weight matrices in one launch (blockIdx.y selects matrix)
__global__ __launch_bounds__(256) void f2h4_w(
    const float* __restrict__ w0, const float* __restrict__ w1,
    const float* __restrict__ w2, const float* __restrict__ w3, int n4)
{
    const float* src = (blockIdx.y == 0) ? w0 : (blockIdx.y == 1) ? w1
                     : (blockIdx.y == 2) ? w2 : w3;
    __half* dst = (blockIdx.y == 0) ? g_wq : (blockIdx.y == 1) ? g_wk
                : (blockIdx.y == 2) ? g_wv : g_wo;
    for (int i = blockIdx.x * 256 + threadIdx.x; i < n4; i += gridDim.x * 256) {
        float4 v = ((const float4*)src)[i];
        ((uint2*)dst)[i] = pack4h(v);
    }
}

// ---------------------------------------------------------------------------
// Projection GEMM core (fp16 m16n8k16 + ldmatrix, half gmem operands,
// 1 sync/iter, reg double buffer). Block 128x128, BK=16, warp tile 64x32.
// ---------------------------------------------------------------------------
template <bool QKV>
__device__ __forceinline__ void gemm_core(
    const __half* __restrict__ Asrc, const __half* __restrict__ W,
    const float* __restrict__ bias, float* __restrict__ dstf,
    __half* __restrict__ dsth,
    int m0, int n0,
    __half (*As)[128][AST], __half (*Bs)[16][BST])
{
    const int tid = threadIdx.x;
    const int wid = tid >> 5, lane = tid & 31;
    const int gid = lane >> 2, tk = lane & 3;
    const int wm = (wid & 1) * 64;
    const int wn = (wid >> 1) * 32;
    const int l15 = lane & 15, lhi = (lane >> 4) * 8;

    const int arow = tid >> 1, ak8 = (tid & 1) * 8;
    const int bkr  = tid >> 4, bn8 = (tid & 15) * 8;
    const bool aval = (m0 + arow < M_);

    float acc[4][4][4];
    #pragma unroll
    for (int mi = 0; mi < 4; mi++)
        #pragma unroll
        for (int ni = 0; ni < 4; ni++)
            #pragma unroll
            for (int r = 0; r < 4; r++) acc[mi][ni][r] = 0.f;

    const uint4 z4 = make_uint4(0u, 0u, 0u, 0u);

    {
        uint4 va = z4;
        if (aval) va = *(const uint4*)(Asrc + (size_t)(m0 + arow) * D_ + ak8);
        uint4 vb = *(const uint4*)(W + (size_t)bkr * D_ + n0 + bn8);
        *(uint4*)&As[0][arow][ak8] = va;
        *(uint4*)&Bs[0][bkr][bn8]  = vb;
    }
    __syncthreads();

    const int NK = D_ / 16;   // 48
    for (int kt = 0; kt < NK; kt++) {
        const int cur = kt & 1;
        const bool pf = (kt + 1 < NK);
        uint4 va = z4, vb = z4;
        if (pf) {
            const int k1 = (kt + 1) * 16;
            if (aval) va = *(const uint4*)(Asrc + (size_t)(m0 + arow) * D_ + k1 + ak8);
            vb = *(const uint4*)(W + (size_t)(k1 + bkr) * D_ + n0 + bn8);
        }

        uint32_t af[4][4];
        #pragma unroll
        for (int mi = 0; mi < 4; mi++)
            ldsm_x4(af[mi][0], af[mi][1], af[mi][2], af[mi][3],
                    &As[cur][wm + mi * 16 + l15][lhi]);
        uint32_t bf[8];
        ldsm_x4_t(bf[0], bf[1], bf[2], bf[3], &Bs[cur][l15][wn + lhi]);
        ldsm_x4_t(bf[4], bf[5], bf[6], bf[7], &Bs[cur][l15][wn + 16 + lhi]);

        #pragma unroll
        for (int mi = 0; mi < 4; mi++) {
            hmma(acc[mi][0], af[mi][0], af[mi][1], af[mi][2], af[mi][3], bf[0], bf[1]);
            hmma(acc[mi][1], af[mi][0], af[mi][1], af[mi][2], af[mi][3], bf[2], bf[3]);
            hmma(acc[mi][2], af[mi][0], af[mi][1], af[mi][2], af[mi][3], bf[4], bf[5]);
            hmma(acc[mi][3], af[mi][0], af[mi][1], af[mi][2], af[mi][3], bf[6], bf[7]);
        }

        if (pf) {
            *(uint4*)&As[cur ^ 1][arow][ak8] = va;
            *(uint4*)&Bs[cur ^ 1][bkr][bn8]  = vb;
        }
        __syncthreads();
    }

    #pragma unroll
    for (int mi = 0; mi < 4; mi++) {
        #pragma unroll
        for (int ni = 0; ni < 4; ni++) {
            const int col = n0 + wn + ni * 8 + 2 * tk;
            const float b0v = bias[col], b1v = bias[col + 1];
            const int r0 = m0 + wm + mi * 16 + gid;
            const int r1 = r0 + 8;
            if (QKV) {
                const int h = col >> 6, hd = col & 63;
                if (r0 < M_) {
                    const int b = r0 / S_, s = r0 - b * S_;
                    *(uint32_t*)(dsth + (((size_t)(b * H_ + h)) * S_ + s) * HD_ + hd) =
                        packh2(acc[mi][ni][0] + b0v, acc[mi][ni][1] + b1v);
                }
                if (r1 < M_) {
                    const int b = r1 / S_, s = r1 - b * S_;
                    *(uint32_t*)(dsth + (((size_t)(b * H_ + h)) * S_ + s) * HD_ + hd) =
                        packh2(acc[mi][ni][2] + b0v, acc[mi][ni][3] + b1v);
                }
            } else {
                if (r0 < M_)
                    *(float2*)(dstf + (size_t)r0 * D_ + col) =
                        make_float2(acc[mi][ni][0] + b0v, acc[mi][ni][1] + b1v);
                if (r1 < M_)
                    *(float2*)(dstf + (size_t)r1 * D_ + col) =
                        make_float2(acc[mi][ni][2] + b0v, acc[mi][ni][3] + b1v);
            }
        }
    }
}

__global__ __launch_bounds__(256, 2) void gemm_qkv(
    const float* __restrict__ bq, const float* __restrict__ bk,
    const float* __restrict__ bv)
{
    __shared__ __align__(16) __half As[2][128][AST];
    __shared__ __align__(16) __half Bs[2][16][BST];
    const int m0  = blockIdx.x * 128;
    const int ng  = blockIdx.y * 128;
    const int mat = ng / D_;
    const int n0  = ng - mat * D_;
    const __half* W   = (mat == 0) ? g_wq : (mat == 1) ? g_wk : g_wv;
    const float* bias = (mat == 0) ? bq : (mat == 1) ? bk : bv;
    __half* dsth = (mat == 0) ? g_qh : (mat == 1) ? g_kh : g_vh;
    gemm_core<true>(g_xh, W, bias, nullptr, dsth, m0, n0, As, Bs);
}

__global__ __launch_bounds__(256, 2) void gemm_out(
    const float* __restrict__ bias, float* __restrict__ out)
{
    __shared__ __align__(16) __half As[2][128][AST];
    __shared__ __align__(16) __half Bs[2][16][BST];
    gemm_core<false>(g_ctxh, g_wo, bias, out, nullptr,
                     blockIdx.x * 128, blockIdx.y * 128, As, Bs);
}

// ---------------------------------------------------------------------------
// Fused attention, 64-row q tile, 512 threads (16 warps, 1 block/SM).
//   scores: Qh [m][k] x Kh [n][k] (non-trans LDSM), 5 chunks of 128 cols
//   softmax: f32 in P (proven)
//   ctx:    P (float2 LDS, PSTR=648 bank-optimal) x Vh [k][n] trans-LDSM
// SMEM: P[64][648] f32 + Qh[64][QSH] + KVh[128][QSH]  (~189 KB)
// ---------------------------------------------------------------------------
__global__ __launch_bounds__(512, 1) void fused_attn(
    float* __restrict__ probs, const int* __restrict__ mask)
{
    extern __shared__ float sm[];
    float*  P   = sm;                                   // [QT][PSTR] f32
    __half* Qh  = (__half*)(sm + QT * PSTR);            // [QT][QSH]
    __half* KVh = Qh + QT * QSH;                        // [128][QSH]

    const int bh  = blockIdx.y;
    const int m0  = blockIdx.x * QT;
    const int tid = threadIdx.x;
    const int wid = tid >> 5, lane = tid & 31;
    const int gid = lane >> 2, tk = lane & 3;
    const int wm  = (wid & 3) * 16;      // 4 warps along m (16 rows each) = 64
    const int wns = (wid >> 2) * 32;     // scores: 4 warps x 32 cols = 128
    const int wnc = (wid >> 2) * 16;     // ctx: 4 warps x 16 cols = 64
    const int l15 = lane & 15, lhi = (lane >> 4) * 8;
    const int brow = (lane & 7) + ((lane & 16) ? 8 : 0);   // non-trans B lane row
    const int bko  = (lane & 8) ? 8 : 0;                    // non-trans B k offset
    const int b   = bh / H_;
    const int h   = bh - b * H_;

    const __half* qb = g_qh + (size_t)bh * S_ * HD_;
    const __half* kb = g_kh + (size_t)bh * S_ * HD_;
    const __half* vb = g_vh + (size_t)bh * S_ * HD_;
    float* pgm = probs + (size_t)bh * S_ * S_;

    // zero pad columns 626..PSTR-1 of P
    for (int i = tid; i < QT * (PSTR - S_); i += 512) {
        const int r = i / (PSTR - S_);
        const int c = S_ + i - r * (PSTR - S_);
        P[r * PSTR + c] = 0.f;
    }

    // load Q tile (QT rows x 64 halves): 1024 uint2, 2 per thread
    #pragma unroll
    for (int i = 0; i < 2; i++) {
        const int idx = tid + i * 512;
        const int row = idx >> 4, c4 = (idx & 15) << 2;
        uint2 v = make_uint2(0u, 0u);
        if (m0 + row < S_) v = *(const uint2*)(qb + (size_t)(m0 + row) * HD_ + c4);
        *(uint2*)&Qh[row * QSH + c4] = v;
    }

    // ---- scores phase: 5 chunks of 128 key-columns ----
    for (int nc = 0; nc < 5; nc++) {
        const int n0 = nc * 128;
        __syncthreads();
        // K tile fill: 128 rows x 64 halves = 2048 uint2, 4 per thread
        #pragma unroll
        for (int i = 0; i < 4; i++) {
            const int idx = tid + i * 512;
            const int row = idx >> 4, c4 = (idx & 15) << 2;
            uint2 v = make_uint2(0u, 0u);
            if (n0 + row < S_) v = *(const uint2*)(kb + (size_t)(n0 + row) * HD_ + c4);
            *(uint2*)&KVh[row * QSH + c4] = v;
        }
        __syncthreads();

        float acc[4][4];
        #pragma unroll
        for (int ni = 0; ni < 4; ni++)
            #pragma unroll
            for (int r = 0; r < 4; r++) acc[ni][r] = 0.f;

        #pragma unroll
        for (int ks = 0; ks < 64; ks += 16) {
            uint32_t a0, a1, a2, a3;
            ldsm_x4(a0, a1, a2, a3, &Qh[(wm + l15) * QSH + ks + lhi]);
            #pragma unroll
            for (int nt = 0; nt < 2; nt++) {
                uint32_t b0, b1, b2, b3;
                ldsm_x4(b0, b1, b2, b3,
                        &KVh[(wns + nt * 16 + brow) * QSH + ks + bko]);
                hmma(acc[nt * 2 + 0], a0, a1, a2, a3, b0, b1);
                hmma(acc[nt * 2 + 1], a0, a1, a2, a3, b2, b3);
            }
        }

        #pragma unroll
        for (int ni = 0; ni < 4; ni++) {
            const int col = n0 + wns + ni * 8 + 2 * tk;   // even
            if (col < S_) {
                *(float2*)&P[(wm + gid    ) * PSTR + col] =
                    make_float2(acc[ni][0] * 0.125f, acc[ni][1] * 0.125f);
                *(float2*)&P[(wm + gid + 8) * PSTR + col] =
                    make_float2(acc[ni][2] * 0.125f, acc[ni][3] * 0.125f);
            }
        }
    }
    __syncthreads();

    // ---- softmax phase (f32): warp w owns rows w*4..w*4+3 (16 warps x 4 = 64) ----
    for (int r = wid * 4; r < wid * 4 + 4; r++) {
        const int q = m0 + r;
        if (q >= S_) break;
        float* row = P + r * PSTR;

        float mx = -3.4e38f;
        for (int i = lane; i < S_; i += 32) mx = fmaxf(mx, row[i]);
        #pragma unroll
        for (int o = 16; o; o >>= 1) mx = fmaxf(mx, __shfl_xor_sync(0xffffffffu, mx, o));

        if (q == 0) {
            const float add = mx * 0.25f;
            for (int i = lane; i < S_; i += 32) {
                const int mk = (i == 0) ? 0 : mask[b * SM1_ + i - 1];
                if (mk == 0) row[i] += add;
            }
            __syncwarp();
            mx = -3.4e38f;
            for (int i = lane; i < S_; i += 32) mx = fmaxf(mx, row[i]);
            #pragma unroll
            for (int o = 16; o; o >>= 1) mx = fmaxf(mx, __shfl_xor_sync(0xffffffffu, mx, o));
        }

        if (lane == 0) g_contrib[(size_t)bh * S_ + q] = row[0];

        float s = 0.f;
        for (int i = lane; i < S_; i += 32) {
            const float e = expf(row[i] - mx);
            row[i] = e;
            s += e;
        }
        #pragma unroll
        for (int o = 16; o; o >>= 1) s += __shfl_xor_sync(0xffffffffu, s, o);
        const float inv = 1.0f / s;

        float* prow = pgm + (size_t)q * S_;
        for (int i = lane; i < S_; i += 32) {
            const float p = row[i] * inv;
            row[i] = p;
            prow[i] = p;
        }
    }
    __syncthreads();

    // ---- ctx phase: 5 chunks of 128 k-rows, fp16 MMA ----
    float cacc[2][4];
    #pragma unroll
    for (int ni = 0; ni < 2; ni++)
        #pragma unroll
        for (int r = 0; r < 4; r++) cacc[ni][r] = 0.f;

    for (int kc = 0; kc < 5; kc++) {
        const int k0 = kc * 128;
        __syncthreads();
        // V tile fill: 128 rows x 64 halves, 4 uint2 per thread
        #pragma unroll
        for (int i = 0; i < 4; i++) {
            const int idx = tid + i * 512;
            const int row = idx >> 4, c4 = (idx & 15) << 2;
            uint2 v = make_uint2(0u, 0u);
            if (k0 + row < S_) v = *(const uint2*)(vb + (size_t)(k0 + row) * HD_ + c4);
            *(uint2*)&KVh[row * QSH + c4] = v;
        }
        __syncthreads();

        #pragma unroll
        for (int ks = 0; ks < 128; ks += 16) {
            const float* pr0 = P + (wm + gid    ) * PSTR + k0 + ks + 2 * tk;
            const float* pr1 = P + (wm + gid + 8) * PSTR + k0 + ks + 2 * tk;
            const float2 v0 = *(const float2*)pr0;
            const float2 v1 = *(const float2*)pr1;
            const float2 v2 = *(const float2*)(pr0 + 8);
            const float2 v3 = *(const float2*)(pr1 + 8);
            const uint32_t a0 = packh2(v0.x, v0.y);
            const uint32_t a1 = packh2(v1.x, v1.y);
            const uint32_t a2 = packh2(v2.x, v2.y);
            const uint32_t a3 = packh2(v3.x, v3.y);
            uint32_t b0, b1, b2, b3;
            ldsm_x4_t(b0, b1, b2, b3, &KVh[(ks + l15) * QSH + wnc + lhi]);
            hmma(cacc[0], a0, a1, a2, a3, b0, b1);
            hmma(cacc[1], a0, a1, a2, a3, b2, b3);
        }
    }

    // ctx epilogue -> half (gemm_out reads half A)
    #pragma unroll
    for (int ni = 0; ni < 2; ni++) {
        const int col = wnc + ni * 8 + 2 * tk;   // even, 0..62
        const int r0 = m0 + wm + gid;
        const int r1 = r0 + 8;
        if (r0 < S_)
            *(uint32_t*)(g_ctxh + ((size_t)(b * S_ + r0)) * D_ + h * HD_ + col) =
                packh2(cacc[ni][0], cacc[ni][1]);
        if (r1 < S_)
            *(uint32_t*)(g_ctxh + ((size_t)(b * S_ + r1)) * D_ + h * HD_ + col) =
                packh2(cacc[ni][2], cacc[ni][3]);
    }
}

// ---------------------------------------------------------------------------
// Contribution: softmax over q of g_contrib[bh, :]
// ---------------------------------------------------------------------------
__global__ __launch_bounds__(256) void contrib_kernel(float* __restrict__ out)
{
    const int bh = blockIdx.x;
    const float* src = g_contrib + (size_t)bh * S_;
    __shared__ float red[8];
    const int tid = threadIdx.x;

    float m = -3.4e38f;
    for (int i = tid; i < S_; i += 256) m = fmaxf(m, src[i]);
    #pragma unroll
    for (int o = 16; o; o >>= 1) m = fmaxf(m, __shfl_xor_sync(0xffffffffu, m, o));
    if ((tid & 31) == 0) red[tid >> 5] = m;
    __syncthreads();
    if (tid == 0) {
        float mm = red[0];
        #pragma unroll
        for (int w = 1; w < 8; w++) mm = fmaxf(mm, red[w]);
        red[0] = mm;
    }
    __syncthreads();
    m = red[0];
    __syncthreads();

    float s = 0.f;
    for (int i = tid; i < S_; i += 256) s += expf(src[i] - m);
    #pragma unroll
    for (int o = 16; o; o >>= 1) s += __shfl_xor_sync(0xffffffffu, s, o);
    if ((tid & 31) == 0) red[tid >> 5] = s;
    __syncthreads();
    if (tid == 0) {
        float ss = 0.f;
        #pragma unroll
        for (int w = 0; w < 8; w++) ss += red[w];
        red[0] = ss;
    }
    __syncthreads();
    const float inv = 1.0f / red[0];
    for (int i = tid; i < S_; i += 256)
        out[(size_t)bh * S_ + i] = expf(src[i] - m) * inv;
}

// ---------------------------------------------------------------------------
// Launch
// ---------------------------------------------------------------------------
extern "C" void kernel_launch(void* const* d_in, const int* in_sizes, int n_in,
                              void* d_out, int out_size)
{
    const float* hs = (const float*)d_in[0];
    const int*  mask = (const int*) d_in[1];
    const float* Wq = (const float*)d_in[2];
    const float* bq = (const float*)d_in[3];
    const float* Wk = (const float*)d_in[4];
    const float* bk = (const float*)d_in[5];
    const float* Wv = (const float*)d_in[6];
    const float* bv = (const float*)d_in[7];
    const float* Wo = (const float*)d_in[8];
    const float* bo = (const float*)d_in[9];

    float* out     = (float*)d_out;
    float* att_out = out;                                       // [B,S,D]
    float* probs   = out + (size_t)M_ * D_;                     // [B,H,S,S]
    float* contrib = probs + (size_t)BH_ * S_ * S_;             // [B,H,S]

    // SMEM: P f32 + Qh half + KVh half (128 rows) = 193,536 B
    const int smem_bytes = QT * PSTR * 4 + QT * QSH * 2 + 128 * QSH * 2;
    cudaFuncSetAttribute(fused_attn,
        cudaFuncAttributeMaxDynamicSharedMemorySize, smem_bytes);

    __half* xh;
    cudaGetSymbolAddress((void**)&xh, g_xh);

    const int nx4 = (M_ * D_) / 4;
    const int nw4 = (D_ * D_) / 4;
    f2h4<<<(nx4 + 255) / 256, 256>>>(hs, xh, nx4);
    f2h4_w<<<dim3(144, 4), 256>>>(Wq, Wk, Wv, Wo, nw4);

    gemm_qkv<<<dim3(79, 18), 256>>>(bq, bk, bv);
    fused_attn<<<dim3(10, 192), 512, smem_bytes>>>(probs, mask);
    contrib_kernel<<<BH_, 256>>>(contrib);
    gemm_out<<<dim3(79, 6), 256>>>(bo, att_out);
}

// round 14
// speedup vs baseline: 1.6018x; 1.0750x over previous
#include <cuda_runtime.h>
#include <cuda_fp16.h>
#include <cstdint>

// Problem constants
#define B_   16
#define S_   626
#define D_   768
#define H_   12
#define HD_  64
#define M_   (B_*S_)          // 10016
#define BH_  (B_*H_)          // 192
#define SM1_ (S_-1)           // 625
#define PSTR 648              // P row stride (floats), 648 % 32 == 8 -> optimal float2 LDS
#define QSH  72               // Qh/Kh/Vh half-tile row stride (halves)
#define QT   64               // q-tile rows in fused_attn (512 threads, 1 block/SM)
#define AST  24               // proj A tile k-stride (halves)
#define BST  136              // proj B tile n-stride (halves)

// Scratch (device globals; no cudaMalloc allowed)
__device__ __half g_qh[BH_*(size_t)S_*HD_];     // q as half [b,h,s,hd]
__device__ __half g_kh[BH_*(size_t)S_*HD_];     // k as half
__device__ __half g_vh[BH_*(size_t)S_*HD_];     // v as half
__device__ __half g_ctxh[(size_t)M_*D_];        // ctx as half
__device__ __half g_xh[(size_t)M_*D_];          // hidden_states as half
__device__ __half g_wq[D_*D_], g_wk[D_*D_], g_wv[D_*D_], g_wo[D_*D_];
__device__ float  g_contrib[BH_*S_];            // fixed scores col 0

// ---------------------------------------------------------------------------
// helpers
// ---------------------------------------------------------------------------
__device__ __forceinline__ void hmma(float c[4],
    uint32_t a0, uint32_t a1, uint32_t a2, uint32_t a3,
    uint32_t b0, uint32_t b1)
{
    asm volatile(
        "mma.sync.aligned.m16n8k16.row.col.f32.f16.f16.f32 "
        "{%0,%1,%2,%3}, {%4,%5,%6,%7}, {%8,%9}, {%0,%1,%2,%3};"
        : "+f"(c[0]), "+f"(c[1]), "+f"(c[2]), "+f"(c[3])
        : "r"(a0), "r"(a1), "r"(a2), "r"(a3), "r"(b0), "r"(b1));
}

__device__ __forceinline__ void ldsm_x4(
    uint32_t& r0, uint32_t& r1, uint32_t& r2, uint32_t& r3, const void* p)
{
    uint32_t a = (uint32_t)__cvta_generic_to_shared(p);
    asm volatile("ldmatrix.sync.aligned.m8n8.x4.shared.b16 {%0,%1,%2,%3}, [%4];"
        : "=r"(r0), "=r"(r1), "=r"(r2), "=r"(r3) : "r"(a));
}

__device__ __forceinline__ void ldsm_x4_t(
    uint32_t& r0, uint32_t& r1, uint32_t& r2, uint32_t& r3, const void* p)
{
    uint32_t a = (uint32_t)__cvta_generic_to_shared(p);
    asm volatile("ldmatrix.sync.aligned.m8n8.x4.trans.shared.b16 {%0,%1,%2,%3}, [%4];"
        : "=r"(r0), "=r"(r1), "=r"(r2), "=r"(r3) : "r"(a));
}

__device__ __forceinline__ uint2 pack4h(float4 v) {
    uint2 u;
    __half2 h;
    h = __floats2half2_rn(v.x, v.y); u.x = *(uint32_t*)&h;
    h = __floats2half2_rn(v.z, v.w); u.y = *(uint32_t*)&h;
    return u;
}

__device__ __forceinline__ uint32_t packh2(float a, float b) {
    __half2 h = __floats2half2_rn(a, b);
    return *(uint32_t*)&h;
}

// ---------------------------------------------------------------------------
// f32 -> f16 bulk conversions
// ---------------------------------------------------------------------------
__global__ __launch_bounds__(256) void f2h4(
    const float* __restrict__ src, __half* __restrict__ dst, int n4)
{
    for (int i = blockIdx.x * 256 + threadIdx.x; i < n4; i += gridDim.x * 256) {
        float4 v = ((const float4*)src)[i];
        ((uint2*)dst)[i] = pack4h(v);
    }
}

__global__ __launch_bounds__(256) void f2h4_w(
    const float* __restrict__ w0, const float* __restrict__ w1,
    const float* __restrict__ w2, const float* __restrict__ w3, int n4)
{
    const float* src = (blockIdx.y == 0) ? w0 : (blockIdx.y == 1) ? w1
                     : (blockIdx.y == 2) ? w2 : w3;
    __half* dst = (blockIdx.y == 0) ? g_wq : (blockIdx.y == 1) ? g_wk
                : (blockIdx.y == 2) ? g_wv : g_wo;
    for (int i = blockIdx.x * 256 + threadIdx.x; i < n4; i += gridDim.x * 256) {
        float4 v = ((const float4*)src)[i];
        ((uint2*)dst)[i] = pack4h(v);
    }
}

// ---------------------------------------------------------------------------
// Projection GEMM core (fp16 m16n8k16 + ldmatrix, half gmem operands,
// 1 sync/iter, reg double buffer). Block 128x128, BK=16, warp tile 64x32.
// ---------------------------------------------------------------------------
template <bool QKV>
__device__ __forceinline__ void gemm_core(
    const __half* __restrict__ Asrc, const __half* __restrict__ W,
    const float* __restrict__ bias, float* __restrict__ dstf,
    __half* __restrict__ dsth,
    int m0, int n0,
    __half (*As)[128][AST], __half (*Bs)[16][BST])
{
    const int tid = threadIdx.x;
    const int wid = tid >> 5, lane = tid & 31;
    const int gid = lane >> 2, tk = lane & 3;
    const int wm = (wid & 1) * 64;
    const int wn = (wid >> 1) * 32;
    const int l15 = lane & 15, lhi = (lane >> 4) * 8;

    const int arow = tid >> 1, ak8 = (tid & 1) * 8;
    const int bkr  = tid >> 4, bn8 = (tid & 15) * 8;
    const bool aval = (m0 + arow < M_);

    float acc[4][4][4];
    #pragma unroll
    for (int mi = 0; mi < 4; mi++)
        #pragma unroll
        for (int ni = 0; ni < 4; ni++)
            #pragma unroll
            for (int r = 0; r < 4; r++) acc[mi][ni][r] = 0.f;

    const uint4 z4 = make_uint4(0u, 0u, 0u, 0u);

    {
        uint4 va = z4;
        if (aval) va = *(const uint4*)(Asrc + (size_t)(m0 + arow) * D_ + ak8);
        uint4 vb = *(const uint4*)(W + (size_t)bkr * D_ + n0 + bn8);
        *(uint4*)&As[0][arow][ak8] = va;
        *(uint4*)&Bs[0][bkr][bn8]  = vb;
    }
    __syncthreads();

    const int NK = D_ / 16;   // 48
    for (int kt = 0; kt < NK; kt++) {
        const int cur = kt & 1;
        const bool pf = (kt + 1 < NK);
        uint4 va = z4, vb = z4;
        if (pf) {
            const int k1 = (kt + 1) * 16;
            if (aval) va = *(const uint4*)(Asrc + (size_t)(m0 + arow) * D_ + k1 + ak8);
            vb = *(const uint4*)(W + (size_t)(k1 + bkr) * D_ + n0 + bn8);
        }

        uint32_t af[4][4];
        #pragma unroll
        for (int mi = 0; mi < 4; mi++)
            ldsm_x4(af[mi][0], af[mi][1], af[mi][2], af[mi][3],
                    &As[cur][wm + mi * 16 + l15][lhi]);
        uint32_t bf[8];
        ldsm_x4_t(bf[0], bf[1], bf[2], bf[3], &Bs[cur][l15][wn + lhi]);
        ldsm_x4_t(bf[4], bf[5], bf[6], bf[7], &Bs[cur][l15][wn + 16 + lhi]);

        #pragma unroll
        for (int mi = 0; mi < 4; mi++) {
            hmma(acc[mi][0], af[mi][0], af[mi][1], af[mi][2], af[mi][3], bf[0], bf[1]);
            hmma(acc[mi][1], af[mi][0], af[mi][1], af[mi][2], af[mi][3], bf[2], bf[3]);
            hmma(acc[mi][2], af[mi][0], af[mi][1], af[mi][2], af[mi][3], bf[4], bf[5]);
            hmma(acc[mi][3], af[mi][0], af[mi][1], af[mi][2], af[mi][3], bf[6], bf[7]);
        }

        if (pf) {
            *(uint4*)&As[cur ^ 1][arow][ak8] = va;
            *(uint4*)&Bs[cur ^ 1][bkr][bn8]  = vb;
        }
        __syncthreads();
    }

    #pragma unroll
    for (int mi = 0; mi < 4; mi++) {
        #pragma unroll
        for (int ni = 0; ni < 4; ni++) {
            const int col = n0 + wn + ni * 8 + 2 * tk;
            const float b0v = bias[col], b1v = bias[col + 1];
            const int r0 = m0 + wm + mi * 16 + gid;
            const int r1 = r0 + 8;
            if (QKV) {
                const int h = col >> 6, hd = col & 63;
                if (r0 < M_) {
                    const int b = r0 / S_, s = r0 - b * S_;
                    *(uint32_t*)(dsth + (((size_t)(b * H_ + h)) * S_ + s) * HD_ + hd) =
                        packh2(acc[mi][ni][0] + b0v, acc[mi][ni][1] + b1v);
                }
                if (r1 < M_) {
                    const int b = r1 / S_, s = r1 - b * S_;
                    *(uint32_t*)(dsth + (((size_t)(b * H_ + h)) * S_ + s) * HD_ + hd) =
                        packh2(acc[mi][ni][2] + b0v, acc[mi][ni][3] + b1v);
                }
            } else {
                if (r0 < M_)
                    *(float2*)(dstf + (size_t)r0 * D_ + col) =
                        make_float2(acc[mi][ni][0] + b0v, acc[mi][ni][1] + b1v);
                if (r1 < M_)
                    *(float2*)(dstf + (size_t)r1 * D_ + col) =
                        make_float2(acc[mi][ni][2] + b0v, acc[mi][ni][3] + b1v);
            }
        }
    }
}

__global__ __launch_bounds__(256, 2) void gemm_qkv(
    const float* __restrict__ bq, const float* __restrict__ bk,
    const float* __restrict__ bv)
{
    __shared__ __align__(16) __half As[2][128][AST];
    __shared__ __align__(16) __half Bs[2][16][BST];
    const int m0  = blockIdx.x * 128;
    const int ng  = blockIdx.y * 128;
    const int mat = ng / D_;
    const int n0  = ng - mat * D_;
    const __half* W   = (mat == 0) ? g_wq : (mat == 1) ? g_wk : g_wv;
    const float* bias = (mat == 0) ? bq : (mat == 1) ? bk : bv;
    __half* dsth = (mat == 0) ? g_qh : (mat == 1) ? g_kh : g_vh;
    gemm_core<true>(g_xh, W, bias, nullptr, dsth, m0, n0, As, Bs);
}

__global__ __launch_bounds__(256, 2) void gemm_out(
    const float* __restrict__ bias, float* __restrict__ out)
{
    __shared__ __align__(16) __half As[2][128][AST];
    __shared__ __align__(16) __half Bs[2][16][BST];
    gemm_core<false>(g_ctxh, g_wo, bias, out, nullptr,
                     blockIdx.x * 128, blockIdx.y * 128, As, Bs);
}

// ---------------------------------------------------------------------------
// Fused attention, 64-row q tile, 512 threads.
//   scores: fp16 LDSM (proven)   softmax: REGISTER-RESIDENT (1 LDS pass + 1 STS pass)
//   ctx:    fp16, float2 P loads (proven)
// ---------------------------------------------------------------------------
__global__ __launch_bounds__(512, 1) void fused_attn(
    float* __restrict__ probs, const int* __restrict__ mask)
{
    extern __shared__ float sm[];
    float*  P   = sm;                                   // [QT][PSTR] f32
    __half* Qh  = (__half*)(sm + QT * PSTR);            // [QT][QSH]
    __half* KVh = Qh + QT * QSH;                        // [128][QSH]

    const int bh  = blockIdx.y;
    const int m0  = blockIdx.x * QT;
    const int tid = threadIdx.x;
    const int wid = tid >> 5, lane = tid & 31;
    const int gid = lane >> 2, tk = lane & 3;
    const int wm  = (wid & 3) * 16;      // 4 warps along m (16 rows each) = 64
    const int wns = (wid >> 2) * 32;     // scores: 4 warps x 32 cols = 128
    const int wnc = (wid >> 2) * 16;     // ctx: 4 warps x 16 cols = 64
    const int l15 = lane & 15, lhi = (lane >> 4) * 8;
    const int brow = (lane & 7) + ((lane & 16) ? 8 : 0);
    const int bko  = (lane & 8) ? 8 : 0;
    const int b   = bh / H_;
    const int h   = bh - b * H_;

    const __half* qb = g_qh + (size_t)bh * S_ * HD_;
    const __half* kb = g_kh + (size_t)bh * S_ * HD_;
    const __half* vb = g_vh + (size_t)bh * S_ * HD_;
    float* pgm = probs + (size_t)bh * S_ * S_;

    // zero pad columns 626..PSTR-1 of P
    for (int i = tid; i < QT * (PSTR - S_); i += 512) {
        const int r = i / (PSTR - S_);
        const int c = S_ + i - r * (PSTR - S_);
        P[r * PSTR + c] = 0.f;
    }

    // load Q tile (QT rows x 64 halves)
    #pragma unroll
    for (int i = 0; i < 2; i++) {
        const int idx = tid + i * 512;
        const int row = idx >> 4, c4 = (idx & 15) << 2;
        uint2 v = make_uint2(0u, 0u);
        if (m0 + row < S_) v = *(const uint2*)(qb + (size_t)(m0 + row) * HD_ + c4);
        *(uint2*)&Qh[row * QSH + c4] = v;
    }

    // ---- scores phase: 5 chunks of 128 key-columns ----
    for (int nc = 0; nc < 5; nc++) {
        const int n0 = nc * 128;
        __syncthreads();
        #pragma unroll
        for (int i = 0; i < 4; i++) {
            const int idx = tid + i * 512;
            const int row = idx >> 4, c4 = (idx & 15) << 2;
            uint2 v = make_uint2(0u, 0u);
            if (n0 + row < S_) v = *(const uint2*)(kb + (size_t)(n0 + row) * HD_ + c4);
            *(uint2*)&KVh[row * QSH + c4] = v;
        }
        __syncthreads();

        float acc[4][4];
        #pragma unroll
        for (int ni = 0; ni < 4; ni++)
            #pragma unroll
            for (int r = 0; r < 4; r++) acc[ni][r] = 0.f;

        #pragma unroll
        for (int ks = 0; ks < 64; ks += 16) {
            uint32_t a0, a1, a2, a3;
            ldsm_x4(a0, a1, a2, a3, &Qh[(wm + l15) * QSH + ks + lhi]);
            #pragma unroll
            for (int nt = 0; nt < 2; nt++) {
                uint32_t b0, b1, b2, b3;
                ldsm_x4(b0, b1, b2, b3,
                        &KVh[(wns + nt * 16 + brow) * QSH + ks + bko]);
                hmma(acc[nt * 2 + 0], a0, a1, a2, a3, b0, b1);
                hmma(acc[nt * 2 + 1], a0, a1, a2, a3, b2, b3);
            }
        }

        #pragma unroll
        for (int ni = 0; ni < 4; ni++) {
            const int col = n0 + wns + ni * 8 + 2 * tk;   // even
            if (col < S_) {
                *(float2*)&P[(wm + gid    ) * PSTR + col] =
                    make_float2(acc[ni][0] * 0.125f, acc[ni][1] * 0.125f);
                *(float2*)&P[(wm + gid + 8) * PSTR + col] =
                    make_float2(acc[ni][2] * 0.125f, acc[ni][3] * 0.125f);
            }
        }
    }
    __syncthreads();

    // ---- softmax phase: register-resident. warp w owns rows w*4..w*4+3 ----
    #define NE 20   // ceil(626/32)
    for (int r = wid * 4; r < wid * 4 + 4; r++) {
        const int q = m0 + r;
        if (q >= S_) break;
        float* row = P + r * PSTR;

        float e[NE];
        #pragma unroll
        for (int j = 0; j < NE; j++) {
            const int i = lane + 32 * j;
            e[j] = (i < S_) ? row[i] : -3.4e38f;
        }

        float mx = -3.4e38f;
        #pragma unroll
        for (int j = 0; j < NE; j++) mx = fmaxf(mx, e[j]);
        #pragma unroll
        for (int o = 16; o; o >>= 1) mx = fmaxf(mx, __shfl_xor_sync(0xffffffffu, mx, o));

        if (q == 0) {
            const float add = mx * 0.25f;
            #pragma unroll
            for (int j = 0; j < NE; j++) {
                const int i = lane + 32 * j;
                if (i < S_) {
                    const int mk = (i == 0) ? 0 : mask[b * SM1_ + i - 1];
                    if (mk == 0) e[j] += add;
                }
            }
            mx = -3.4e38f;
            #pragma unroll
            for (int j = 0; j < NE; j++) mx = fmaxf(mx, e[j]);
            #pragma unroll
            for (int o = 16; o; o >>= 1) mx = fmaxf(mx, __shfl_xor_sync(0xffffffffu, mx, o));
        }

        if (lane == 0) g_contrib[(size_t)bh * S_ + q] = e[0];   // fixed score at k=0

        float s = 0.f;
        #pragma unroll
        for (int j = 0; j < NE; j++) {
            const int i = lane + 32 * j;
            const float v = (i < S_) ? expf(e[j] - mx) : 0.f;
            e[j] = v;
            s += v;
        }
        #pragma unroll
        for (int o = 16; o; o >>= 1) s += __shfl_xor_sync(0xffffffffu, s, o);
        const float inv = 1.0f / s;

        float* prow = pgm + (size_t)q * S_;
        #pragma unroll
        for (int j = 0; j < NE; j++) {
            const int i = lane + 32 * j;
            if (i < S_) {
                const float p = e[j] * inv;
                row[i] = p;
                prow[i] = p;
            }
        }
    }
    #undef NE
    __syncthreads();

    // ---- ctx phase: 5 chunks of 128 k-rows, fp16 MMA ----
    float cacc[2][4];
    #pragma unroll
    for (int ni = 0; ni < 2; ni++)
        #pragma unroll
        for (int r = 0; r < 4; r++) cacc[ni][r] = 0.f;

    for (int kc = 0; kc < 5; kc++) {
        const int k0 = kc * 128;
        __syncthreads();
        #pragma unroll
        for (int i = 0; i < 4; i++) {
            const int idx = tid + i * 512;
            const int row = idx >> 4, c4 = (idx & 15) << 2;
            uint2 v = make_uint2(0u, 0u);
            if (k0 + row < S_) v = *(const uint2*)(vb + (size_t)(k0 + row) * HD_ + c4);
            *(uint2*)&KVh[row * QSH + c4] = v;
        }
        __syncthreads();

        #pragma unroll
        for (int ks = 0; ks < 128; ks += 16) {
            const float* pr0 = P + (wm + gid    ) * PSTR + k0 + ks + 2 * tk;
            const float* pr1 = P + (wm + gid + 8) * PSTR + k0 + ks + 2 * tk;
            const float2 v0 = *(const float2*)pr0;
            const float2 v1 = *(const float2*)pr1;
            const float2 v2 = *(const float2*)(pr0 + 8);
            const float2 v3 = *(const float2*)(pr1 + 8);
            const uint32_t a0 = packh2(v0.x, v0.y);
            const uint32_t a1 = packh2(v1.x, v1.y);
            const uint32_t a2 = packh2(v2.x, v2.y);
            const uint32_t a3 = packh2(v3.x, v3.y);
            uint32_t b0, b1, b2, b3;
            ldsm_x4_t(b0, b1, b2, b3, &KVh[(ks + l15) * QSH + wnc + lhi]);
            hmma(cacc[0], a0, a1, a2, a3, b0, b1);
            hmma(cacc[1], a0, a1, a2, a3, b2, b3);
        }
    }

    // ctx epilogue -> half (gemm_out reads half A)
    #pragma unroll
    for (int ni = 0; ni < 2; ni++) {
        const int col = wnc + ni * 8 + 2 * tk;   // even, 0..62
        const int r0 = m0 + wm + gid;
        const int r1 = r0 + 8;
        if (r0 < S_)
            *(uint32_t*)(g_ctxh + ((size_t)(b * S_ + r0)) * D_ + h * HD_ + col) =
                packh2(cacc[ni][0], cacc[ni][1]);
        if (r1 < S_)
            *(uint32_t*)(g_ctxh + ((size_t)(b * S_ + r1)) * D_ + h * HD_ + col) =
                packh2(cacc[ni][2], cacc[ni][3]);
    }
}

// ---------------------------------------------------------------------------
// Contribution: softmax over q of g_contrib[bh, :]
// ---------------------------------------------------------------------------
__global__ __launch_bounds__(256) void contrib_kernel(float* __restrict__ out)
{
    const int bh = blockIdx.x;
    const float* src = g_contrib + (size_t)bh * S_;
    __shared__ float red[8];
    const int tid = threadIdx.x;

    float m = -3.4e38f;
    for (int i = tid; i < S_; i += 256) m = fmaxf(m, src[i]);
    #pragma unroll
    for (int o = 16; o; o >>= 1) m = fmaxf(m, __shfl_xor_sync(0xffffffffu, m, o));
    if ((tid & 31) == 0) red[tid >> 5] = m;
    __syncthreads();
    if (tid == 0) {
        float mm = red[0];
        #pragma unroll
        for (int w = 1; w < 8; w++) mm = fmaxf(mm, red[w]);
        red[0] = mm;
    }
    __syncthreads();
    m = red[0];
    __syncthreads();

    float s = 0.f;
    for (int i = tid; i < S_; i += 256) s += expf(src[i] - m);
    #pragma unroll
    for (int o = 16; o; o >>= 1) s += __shfl_xor_sync(0xffffffffu, s, o);
    if ((tid & 31) == 0) red[tid >> 5] = s;
    __syncthreads();
    if (tid == 0) {
        float ss = 0.f;
        #pragma unroll
        for (int w = 0; w < 8; w++) ss += red[w];
        red[0] = ss;
    }
    __syncthreads();
    const float inv = 1.0f / red[0];
    for (int i = tid; i < S_; i += 256)
        out[(size_t)bh * S_ + i] = expf(src[i] - m) * inv;
}

// ---------------------------------------------------------------------------
// Launch
// ---------------------------------------------------------------------------
extern "C" void kernel_launch(void* const* d_in, const int* in_sizes, int n_in,
                              void* d_out, int out_size)
{
    const float* hs = (const float*)d_in[0];
    const int*  mask = (const int*) d_in[1];
    const float* Wq = (const float*)d_in[2];
    const float* bq = (const float*)d_in[3];
    const float* Wk = (const float*)d_in[4];
    const float* bk = (const float*)d_in[5];
    const float* Wv = (const float*)d_in[6];
    const float* bv = (const float*)d_in[7];
    const float* Wo = (const float*)d_in[8];
    const float* bo = (const float*)d_in[9];

    float* out     = (float*)d_out;
    float* att_out = out;                                       // [B,S,D]
    float* probs   = out + (size_t)M_ * D_;                     // [B,H,S,S]
    float* contrib = probs + (size_t)BH_ * S_ * S_;             // [B,H,S]

    const int smem_bytes = QT * PSTR * 4 + QT * QSH * 2 + 128 * QSH * 2;
    cudaFuncSetAttribute(fused_attn,
        cudaFuncAttributeMaxDynamicSharedMemorySize, smem_bytes);

    __half* xh;
    cudaGetSymbolAddress((void**)&xh, g_xh);

    const int nx4 = (M_ * D_) / 4;
    const int nw4 = (D_ * D_) / 4;
    f2h4<<<(nx4 + 255) / 256, 256>>>(hs, xh, nx4);
    f2h4_w<<<dim3(144, 4), 256>>>(Wq, Wk, Wv, Wo, nw4);

    gemm_qkv<<<dim3(79, 18), 256>>>(bq, bk, bv);
    fused_attn<<<dim3(10, 192), 512, smem_bytes>>>(probs, mask);
    contrib_kernel<<<BH_, 256>>>(contrib);
    gemm_out<<<dim3(79, 6), 256>>>(bo, att_out);
}

// round 15
// speedup vs baseline: 1.6838x; 1.0512x over previous
#include <cuda_runtime.h>
#include <cuda_fp16.h>
#include <cstdint>

// Problem constants
#define B_   16
#define S_   626
#define D_   768
#define H_   12
#define HD_  64
#define M_   (B_*S_)          // 10016
#define BH_  (B_*H_)          // 192
#define SM1_ (S_-1)           // 625
#define PSTR 644              // P row stride (floats); 644%32==4 -> Ph LDSM conflict-free
#define QSH  72               // Qh/Kh/Vh half-tile row stride (halves)
#define QT   64               // q-tile rows in fused_attn (512 threads, 1 block/SM)
#define AST  24               // proj A tile k-stride (halves)
#define BST  136              // proj B tile n-stride (halves)

// Scratch (device globals; no cudaMalloc allowed)
__device__ __half g_qh[BH_*(size_t)S_*HD_];     // q as half [b,h,s,hd]
__device__ __half g_kh[BH_*(size_t)S_*HD_];     // k as half
__device__ __half g_vh[BH_*(size_t)S_*HD_];     // v as half
__device__ __half g_ctxh[(size_t)M_*D_];        // ctx as half
__device__ __half g_xh[(size_t)M_*D_];          // hidden_states as half
__device__ __half g_wq[D_*D_], g_wk[D_*D_], g_wv[D_*D_], g_wo[D_*D_];
__device__ float  g_contrib[BH_*S_];            // fixed scores col 0

// ---------------------------------------------------------------------------
// helpers
// ---------------------------------------------------------------------------
__device__ __forceinline__ void hmma(float c[4],
    uint32_t a0, uint32_t a1, uint32_t a2, uint32_t a3,
    uint32_t b0, uint32_t b1)
{
    asm volatile(
        "mma.sync.aligned.m16n8k16.row.col.f32.f16.f16.f32 "
        "{%0,%1,%2,%3}, {%4,%5,%6,%7}, {%8,%9}, {%0,%1,%2,%3};"
        : "+f"(c[0]), "+f"(c[1]), "+f"(c[2]), "+f"(c[3])
        : "r"(a0), "r"(a1), "r"(a2), "r"(a3), "r"(b0), "r"(b1));
}

__device__ __forceinline__ void ldsm_x4(
    uint32_t& r0, uint32_t& r1, uint32_t& r2, uint32_t& r3, const void* p)
{
    uint32_t a = (uint32_t)__cvta_generic_to_shared(p);
    asm volatile("ldmatrix.sync.aligned.m8n8.x4.shared.b16 {%0,%1,%2,%3}, [%4];"
        : "=r"(r0), "=r"(r1), "=r"(r2), "=r"(r3) : "r"(a));
}

__device__ __forceinline__ void ldsm_x4_t(
    uint32_t& r0, uint32_t& r1, uint32_t& r2, uint32_t& r3, const void* p)
{
    uint32_t a = (uint32_t)__cvta_generic_to_shared(p);
    asm volatile("ldmatrix.sync.aligned.m8n8.x4.trans.shared.b16 {%0,%1,%2,%3}, [%4];"
        : "=r"(r0), "=r"(r1), "=r"(r2), "=r"(r3) : "r"(a));
}

__device__ __forceinline__ uint2 pack4h(float4 v) {
    uint2 u;
    __half2 h;
    h = __floats2half2_rn(v.x, v.y); u.x = *(uint32_t*)&h;
    h = __floats2half2_rn(v.z, v.w); u.y = *(uint32_t*)&h;
    return u;
}

__device__ __forceinline__ uint32_t packh2(float a, float b) {
    __half2 h = __floats2half2_rn(a, b);
    return *(uint32_t*)&h;
}

// ---------------------------------------------------------------------------
// f32 -> f16 bulk conversions
// ---------------------------------------------------------------------------
__global__ __launch_bounds__(256) void f2h4(
    const float* __restrict__ src, __half* __restrict__ dst, int n4)
{
    for (int i = blockIdx.x * 256 + threadIdx.x; i < n4; i += gridDim.x * 256) {
        float4 v = ((const float4*)src)[i];
        ((uint2*)dst)[i] = pack4h(v);
    }
}

__global__ __launch_bounds__(256) void f2h4_w(
    const float* __restrict__ w0, const float* __restrict__ w1,
    const float* __restrict__ w2, const float* __restrict__ w3, int n4)
{
    const float* src = (blockIdx.y == 0) ? w0 : (blockIdx.y == 1) ? w1
                     : (blockIdx.y == 2) ? w2 : w3;
    __half* dst = (blockIdx.y == 0) ? g_wq : (blockIdx.y == 1) ? g_wk
                : (blockIdx.y == 2) ? g_wv : g_wo;
    for (int i = blockIdx.x * 256 + threadIdx.x; i < n4; i += gridDim.x * 256) {
        float4 v = ((const float4*)src)[i];
        ((uint2*)dst)[i] = pack4h(v);
    }
}

// ---------------------------------------------------------------------------
// Projection GEMM core (fp16 m16n8k16 + ldmatrix, half gmem operands,
// 1 sync/iter, reg double buffer). Block 128x128, BK=16, warp tile 64x32.
// ---------------------------------------------------------------------------
template <bool QKV>
__device__ __forceinline__ void gemm_core(
    const __half* __restrict__ Asrc, const __half* __restrict__ W,
    const float* __restrict__ bias, float* __restrict__ dstf,
    __half* __restrict__ dsth,
    int m0, int n0,
    __half (*As)[128][AST], __half (*Bs)[16][BST])
{
    const int tid = threadIdx.x;
    const int wid = tid >> 5, lane = tid & 31;
    const int gid = lane >> 2, tk = lane & 3;
    const int wm = (wid & 1) * 64;
    const int wn = (wid >> 1) * 32;
    const int l15 = lane & 15, lhi = (lane >> 4) * 8;

    const int arow = tid >> 1, ak8 = (tid & 1) * 8;
    const int bkr  = tid >> 4, bn8 = (tid & 15) * 8;
    const bool aval = (m0 + arow < M_);

    float acc[4][4][4];
    #pragma unroll
    for (int mi = 0; mi < 4; mi++)
        #pragma unroll
        for (int ni = 0; ni < 4; ni++)
            #pragma unroll
            for (int r = 0; r < 4; r++) acc[mi][ni][r] = 0.f;

    const uint4 z4 = make_uint4(0u, 0u, 0u, 0u);

    {
        uint4 va = z4;
        if (aval) va = *(const uint4*)(Asrc + (size_t)(m0 + arow) * D_ + ak8);
        uint4 vb = *(const uint4*)(W + (size_t)bkr * D_ + n0 + bn8);
        *(uint4*)&As[0][arow][ak8] = va;
        *(uint4*)&Bs[0][bkr][bn8]  = vb;
    }
    __syncthreads();

    const int NK = D_ / 16;   // 48
    for (int kt = 0; kt < NK; kt++) {
        const int cur = kt & 1;
        const bool pf = (kt + 1 < NK);
        uint4 va = z4, vb = z4;
        if (pf) {
            const int k1 = (kt + 1) * 16;
            if (aval) va = *(const uint4*)(Asrc + (size_t)(m0 + arow) * D_ + k1 + ak8);
            vb = *(const uint4*)(W + (size_t)(k1 + bkr) * D_ + n0 + bn8);
        }

        uint32_t af[4][4];
        #pragma unroll
        for (int mi = 0; mi < 4; mi++)
            ldsm_x4(af[mi][0], af[mi][1], af[mi][2], af[mi][3],
                    &As[cur][wm + mi * 16 + l15][lhi]);
        uint32_t bf[8];
        ldsm_x4_t(bf[0], bf[1], bf[2], bf[3], &Bs[cur][l15][wn + lhi]);
        ldsm_x4_t(bf[4], bf[5], bf[6], bf[7], &Bs[cur][l15][wn + 16 + lhi]);

        #pragma unroll
        for (int mi = 0; mi < 4; mi++) {
            hmma(acc[mi][0], af[mi][0], af[mi][1], af[mi][2], af[mi][3], bf[0], bf[1]);
            hmma(acc[mi][1], af[mi][0], af[mi][1], af[mi][2], af[mi][3], bf[2], bf[3]);
            hmma(acc[mi][2], af[mi][0], af[mi][1], af[mi][2], af[mi][3], bf[4], bf[5]);
            hmma(acc[mi][3], af[mi][0], af[mi][1], af[mi][2], af[mi][3], bf[6], bf[7]);
        }

        if (pf) {
            *(uint4*)&As[cur ^ 1][arow][ak8] = va;
            *(uint4*)&Bs[cur ^ 1][bkr][bn8]  = vb;
        }
        __syncthreads();
    }

    #pragma unroll
    for (int mi = 0; mi < 4; mi++) {
        #pragma unroll
        for (int ni = 0; ni < 4; ni++) {
            const int col = n0 + wn + ni * 8 + 2 * tk;
            const float b0v = bias[col], b1v = bias[col + 1];
            const int r0 = m0 + wm + mi * 16 + gid;
            const int r1 = r0 + 8;
            if (QKV) {
                const int h = col >> 6, hd = col & 63;
                if (r0 < M_) {
                    const int b = r0 / S_, s = r0 - b * S_;
                    *(uint32_t*)(dsth + (((size_t)(b * H_ + h)) * S_ + s) * HD_ + hd) =
                        packh2(acc[mi][ni][0] + b0v, acc[mi][ni][1] + b1v);
                }
                if (r1 < M_) {
                    const int b = r1 / S_, s = r1 - b * S_;
                    *(uint32_t*)(dsth + (((size_t)(b * H_ + h)) * S_ + s) * HD_ + hd) =
                        packh2(acc[mi][ni][2] + b0v, acc[mi][ni][3] + b1v);
                }
            } else {
                if (r0 < M_)
                    *(float2*)(dstf + (size_t)r0 * D_ + col) =
                        make_float2(acc[mi][ni][0] + b0v, acc[mi][ni][1] + b1v);
                if (r1 < M_)
                    *(float2*)(dstf + (size_t)r1 * D_ + col) =
                        make_float2(acc[mi][ni][2] + b0v, acc[mi][ni][3] + b1v);
            }
        }
    }
}

__global__ __launch_bounds__(256, 2) void gemm_qkv(
    const float* __restrict__ bq, const float* __restrict__ bk,
    const float* __restrict__ bv)
{
    __shared__ __align__(16) __half As[2][128][AST];
    __shared__ __align__(16) __half Bs[2][16][BST];
    const int m0  = blockIdx.x * 128;
    const int ng  = blockIdx.y * 128;
    const int mat = ng / D_;
    const int n0  = ng - mat * D_;
    const __half* W   = (mat == 0) ? g_wq : (mat == 1) ? g_wk : g_wv;
    const float* bias = (mat == 0) ? bq : (mat == 1) ? bk : bv;
    __half* dsth = (mat == 0) ? g_qh : (mat == 1) ? g_kh : g_vh;
    gemm_core<true>(g_xh, W, bias, nullptr, dsth, m0, n0, As, Bs);
}

__global__ __launch_bounds__(256, 2) void gemm_out(
    const float* __restrict__ bias, float* __restrict__ out)
{
    __shared__ __align__(16) __half As[2][128][AST];
    __shared__ __align__(16) __half Bs[2][16][BST];
    gemm_core<false>(g_ctxh, g_wo, bias, out, nullptr,
                     blockIdx.x * 128, blockIdx.y * 128, As, Bs);
}

// ---------------------------------------------------------------------------
// Fused attention, 64-row q tile, 512 threads.
//   scores: fp16 LDSM (proven)
//   softmax: register-resident; writes normalized probs as HALF in place at
//            the front of each f32 P row (Ph row r overlays f32 row r only)
//   ctx:    A-operand via non-trans LDSM on Ph; B (V) via trans LDSM (proven)
// ---------------------------------------------------------------------------
__global__ __launch_bounds__(512, 1) void fused_attn(
    float* __restrict__ probs, const int* __restrict__ mask)
{
    extern __shared__ float sm[];
    float*  P   = sm;                                   // [QT][PSTR] f32
    __half* Qh  = (__half*)(sm + QT * PSTR);            // [QT][QSH]
    __half* KVh = Qh + QT * QSH;                        // [128][QSH]

    const int bh  = blockIdx.y;
    const int m0  = blockIdx.x * QT;
    const int tid = threadIdx.x;
    const int wid = tid >> 5, lane = tid & 31;
    const int gid = lane >> 2, tk = lane & 3;
    const int wm  = (wid & 3) * 16;      // 4 warps along m (16 rows each) = 64
    const int wns = (wid >> 2) * 32;     // scores: 4 warps x 32 cols = 128
    const int wnc = (wid >> 2) * 16;     // ctx: 4 warps x 16 cols = 64
    const int l15 = lane & 15, lhi = (lane >> 4) * 8;
    const int brow = (lane & 7) + ((lane & 16) ? 8 : 0);
    const int bko  = (lane & 8) ? 8 : 0;
    const int b   = bh / H_;
    const int h   = bh - b * H_;

    const __half* qb = g_qh + (size_t)bh * S_ * HD_;
    const __half* kb = g_kh + (size_t)bh * S_ * HD_;
    const __half* vb = g_vh + (size_t)bh * S_ * HD_;
    float* pgm = probs + (size_t)bh * S_ * S_;

    // load Q tile (QT rows x 64 halves)
    #pragma unroll
    for (int i = 0; i < 2; i++) {
        const int idx = tid + i * 512;
        const int row = idx >> 4, c4 = (idx & 15) << 2;
        uint2 v = make_uint2(0u, 0u);
        if (m0 + row < S_) v = *(const uint2*)(qb + (size_t)(m0 + row) * HD_ + c4);
        *(uint2*)&Qh[row * QSH + c4] = v;
    }

    // ---- scores phase: 5 chunks of 128 key-columns ----
    for (int nc = 0; nc < 5; nc++) {
        const int n0 = nc * 128;
        __syncthreads();
        #pragma unroll
        for (int i = 0; i < 4; i++) {
            const int idx = tid + i * 512;
            const int row = idx >> 4, c4 = (idx & 15) << 2;
            uint2 v = make_uint2(0u, 0u);
            if (n0 + row < S_) v = *(const uint2*)(kb + (size_t)(n0 + row) * HD_ + c4);
            *(uint2*)&KVh[row * QSH + c4] = v;
        }
        __syncthreads();

        float acc[4][4];
        #pragma unroll
        for (int ni = 0; ni < 4; ni++)
            #pragma unroll
            for (int r = 0; r < 4; r++) acc[ni][r] = 0.f;

        #pragma unroll
        for (int ks = 0; ks < 64; ks += 16) {
            uint32_t a0, a1, a2, a3;
            ldsm_x4(a0, a1, a2, a3, &Qh[(wm + l15) * QSH + ks + lhi]);
            #pragma unroll
            for (int nt = 0; nt < 2; nt++) {
                uint32_t b0, b1, b2, b3;
                ldsm_x4(b0, b1, b2, b3,
                        &KVh[(wns + nt * 16 + brow) * QSH + ks + bko]);
                hmma(acc[nt * 2 + 0], a0, a1, a2, a3, b0, b1);
                hmma(acc[nt * 2 + 1], a0, a1, a2, a3, b2, b3);
            }
        }

        #pragma unroll
        for (int ni = 0; ni < 4; ni++) {
            const int col = n0 + wns + ni * 8 + 2 * tk;   // even
            if (col < S_) {
                *(float2*)&P[(wm + gid    ) * PSTR + col] =
                    make_float2(acc[ni][0] * 0.125f, acc[ni][1] * 0.125f);
                *(float2*)&P[(wm + gid + 8) * PSTR + col] =
                    make_float2(acc[ni][2] * 0.125f, acc[ni][3] * 0.125f);
            }
        }
    }
    __syncthreads();

    // ---- softmax phase: register-resident; warp w owns rows w*4..w*4+3.
    //      Output written as HALF in place (Ph row r = front of f32 row r).
    #define NE 20   // ceil(626/32); covers columns 0..639 for padding
    for (int r = wid * 4; r < wid * 4 + 4; r++) {
        const int q = m0 + r;
        if (q >= S_) break;
        float* row = P + (size_t)r * PSTR;

        float e[NE];
        #pragma unroll
        for (int j = 0; j < NE; j++) {
            const int i = lane + 32 * j;
            e[j] = (i < S_) ? row[i] : -3.4e38f;
        }

        float mx = -3.4e38f;
        #pragma unroll
        for (int j = 0; j < NE; j++) mx = fmaxf(mx, e[j]);
        #pragma unroll
        for (int o = 16; o; o >>= 1) mx = fmaxf(mx, __shfl_xor_sync(0xffffffffu, mx, o));

        if (q == 0) {
            const float add = mx * 0.25f;
            #pragma unroll
            for (int j = 0; j < NE; j++) {
                const int i = lane + 32 * j;
                if (i < S_) {
                    const int mk = (i == 0) ? 0 : mask[b * SM1_ + i - 1];
                    if (mk == 0) e[j] += add;
                }
            }
            mx = -3.4e38f;
            #pragma unroll
            for (int j = 0; j < NE; j++) mx = fmaxf(mx, e[j]);
            #pragma unroll
            for (int o = 16; o; o >>= 1) mx = fmaxf(mx, __shfl_xor_sync(0xffffffffu, mx, o));
        }

        if (lane == 0) g_contrib[(size_t)bh * S_ + q] = e[0];   // fixed score at k=0

        float s = 0.f;
        #pragma unroll
        for (int j = 0; j < NE; j++) {
            const int i = lane + 32 * j;
            const float v = (i < S_) ? __expf(e[j] - mx) : 0.f;
            e[j] = v;
            s += v;
        }
        #pragma unroll
        for (int o = 16; o; o >>= 1) s += __shfl_xor_sync(0xffffffffu, s, o);
        const float inv = 1.0f / s;

        // ensure all f32 reads of this row precede the aliasing half writes
        asm volatile("" ::: "memory");

        __half* ph = (__half*)row;                    // overlays this row only
        float* prow = pgm + (size_t)q * S_;
        #pragma unroll
        for (int j = 0; j < NE; j++) {
            const int i = lane + 32 * j;
            if (i < S_) {
                const float p = e[j] * inv;
                ph[i] = __float2half_rn(p);
                prow[i] = p;
            } else {
                ph[i] = __float2half_rn(0.f * inv);   // pad cols 626..639
            }
        }
    }
    #undef NE
    __syncthreads();

    // ---- ctx phase: 5 chunks of 128 k-rows, fp16 MMA, A via LDSM on Ph ----
    float cacc[2][4];
    #pragma unroll
    for (int ni = 0; ni < 2; ni++)
        #pragma unroll
        for (int r = 0; r < 4; r++) cacc[ni][r] = 0.f;

    const __half* Ph = (const __half*)P;              // row stride 2*PSTR halves

    for (int kc = 0; kc < 5; kc++) {
        const int k0 = kc * 128;
        __syncthreads();
        #pragma unroll
        for (int i = 0; i < 4; i++) {
            const int idx = tid + i * 512;
            const int row = idx >> 4, c4 = (idx & 15) << 2;
            uint2 v = make_uint2(0u, 0u);
            if (k0 + row < S_) v = *(const uint2*)(vb + (size_t)(k0 + row) * HD_ + c4);
            *(uint2*)&KVh[row * QSH + c4] = v;
        }
        __syncthreads();

        #pragma unroll
        for (int ks = 0; ks < 128; ks += 16) {
            uint32_t a0, a1, a2, a3;
            ldsm_x4(a0, a1, a2, a3,
                    &Ph[(size_t)(wm + l15) * (2 * PSTR) + k0 + ks + lhi]);
            uint32_t b0, b1, b2, b3;
            ldsm_x4_t(b0, b1, b2, b3, &KVh[(ks + l15) * QSH + wnc + lhi]);
            hmma(cacc[0], a0, a1, a2, a3, b0, b1);
            hmma(cacc[1], a0, a1, a2, a3, b2, b3);
        }
    }

    // ctx epilogue -> half (gemm_out reads half A)
    #pragma unroll
    for (int ni = 0; ni < 2; ni++) {
        const int col = wnc + ni * 8 + 2 * tk;   // even, 0..62
        const int r0 = m0 + wm + gid;
        const int r1 = r0 + 8;
        if (r0 < S_)
            *(uint32_t*)(g_ctxh + ((size_t)(b * S_ + r0)) * D_ + h * HD_ + col) =
                packh2(cacc[ni][0], cacc[ni][1]);
        if (r1 < S_)
            *(uint32_t*)(g_ctxh + ((size_t)(b * S_ + r1)) * D_ + h * HD_ + col) =
                packh2(cacc[ni][2], cacc[ni][3]);
    }
}

// ---------------------------------------------------------------------------
// Contribution: softmax over q of g_contrib[bh, :]
// ---------------------------------------------------------------------------
__global__ __launch_bounds__(256) void contrib_kernel(float* __restrict__ out)
{
    const int bh = blockIdx.x;
    const float* src = g_contrib + (size_t)bh * S_;
    __shared__ float red[8];
    const int tid = threadIdx.x;

    float m = -3.4e38f;
    for (int i = tid; i < S_; i += 256) m = fmaxf(m, src[i]);
    #pragma unroll
    for (int o = 16; o; o >>= 1) m = fmaxf(m, __shfl_xor_sync(0xffffffffu, m, o));
    if ((tid & 31) == 0) red[tid >> 5] = m;
    __syncthreads();
    if (tid == 0) {
        float mm = red[0];
        #pragma unroll
        for (int w = 1; w < 8; w++) mm = fmaxf(mm, red[w]);
        red[0] = mm;
    }
    __syncthreads();
    m = red[0];
    __syncthreads();

    float s = 0.f;
    for (int i = tid; i < S_; i += 256) s += expf(src[i] - m);
    #pragma unroll
    for (int o = 16; o; o >>= 1) s += __shfl_xor_sync(0xffffffffu, s, o);
    if ((tid & 31) == 0) red[tid >> 5] = s;
    __syncthreads();
    if (tid == 0) {
        float ss = 0.f;
        #pragma unroll
        for (int w = 0; w < 8; w++) ss += red[w];
        red[0] = ss;
    }
    __syncthreads();
    const float inv = 1.0f / red[0];
    for (int i = tid; i < S_; i += 256)
        out[(size_t)bh * S_ + i] = expf(src[i] - m) * inv;
}

// ---------------------------------------------------------------------------
// Launch
// ---------------------------------------------------------------------------
extern "C" void kernel_launch(void* const* d_in, const int* in_sizes, int n_in,
                              void* d_out, int out_size)
{
    const float* hs = (const float*)d_in[0];
    const int*  mask = (const int*) d_in[1];
    const float* Wq = (const float*)d_in[2];
    const float* bq = (const float*)d_in[3];
    const float* Wk = (const float*)d_in[4];
    const float* bk = (const float*)d_in[5];
    const float* Wv = (const float*)d_in[6];
    const float* bv = (const float*)d_in[7];
    const float* Wo = (const float*)d_in[8];
    const float* bo = (const float*)d_in[9];

    float* out     = (float*)d_out;
    float* att_out = out;                                       // [B,S,D]
    float* probs   = out + (size_t)M_ * D_;                     // [B,H,S,S]
    float* contrib = probs + (size_t)BH_ * S_ * S_;             // [B,H,S]

    const int smem_bytes = QT * PSTR * 4 + QT * QSH * 2 + 128 * QSH * 2;
    cudaFuncSetAttribute(fused_attn,
        cudaFuncAttributeMaxDynamicSharedMemorySize, smem_bytes);

    __half* xh;
    cudaGetSymbolAddress((void**)&xh, g_xh);

    const int nx4 = (M_ * D_) / 4;
    const int nw4 = (D_ * D_) / 4;
    f2h4<<<(nx4 + 255) / 256, 256>>>(hs, xh, nx4);
    f2h4_w<<<dim3(144, 4), 256>>>(Wq, Wk, Wv, Wo, nw4);

    gemm_qkv<<<dim3(79, 18), 256>>>(bq, bk, bv);
    fused_attn<<<dim3(10, 192), 512, smem_bytes>>>(probs, mask);
    contrib_kernel<<<BH_, 256>>>(contrib);
    gemm_out<<<dim3(79, 6), 256>>>(bo, att_out);
}

// round 16
// speedup vs baseline: 1.7866x; 1.0610x over previous
#include <cuda_runtime.h>
#include <cuda_fp16.h>
#include <cstdint>

// Problem constants
#define B_   16
#define S_   626
#define D_   768
#define H_   12
#define HD_  64
#define M_   (B_*S_)          // 10016
#define BH_  (B_*H_)          // 192
#define SM1_ (S_-1)           // 625
#define PSTR 644              // P row stride (floats); 644%32==4 -> Ph LDSM conflict-free
#define QSH  72               // Qh/Kh/Vh half-tile row stride (halves)
#define QT   64               // q-tile rows in fused_attn (512 threads, 1 block/SM)
#define AST  24               // proj A tile k-stride (halves)
#define BST  136              // proj B tile n-stride (halves)

// Scratch (device globals; no cudaMalloc allowed)
__device__ __half g_qh[BH_*(size_t)S_*HD_];     // q as half [b,h,s,hd]
__device__ __half g_kh[BH_*(size_t)S_*HD_];     // k as half
__device__ __half g_vh[BH_*(size_t)S_*HD_];     // v as half
__device__ __half g_ctxh[(size_t)M_*D_];        // ctx as half
__device__ __half g_xh[(size_t)M_*D_];          // hidden_states as half
__device__ __half g_wq[D_*D_], g_wk[D_*D_], g_wv[D_*D_], g_wo[D_*D_];
__device__ float  g_contrib[BH_*S_];            // fixed scores col 0

// ---------------------------------------------------------------------------
// helpers
// ---------------------------------------------------------------------------
__device__ __forceinline__ void hmma(float c[4],
    uint32_t a0, uint32_t a1, uint32_t a2, uint32_t a3,
    uint32_t b0, uint32_t b1)
{
    asm volatile(
        "mma.sync.aligned.m16n8k16.row.col.f32.f16.f16.f32 "
        "{%0,%1,%2,%3}, {%4,%5,%6,%7}, {%8,%9}, {%0,%1,%2,%3};"
        : "+f"(c[0]), "+f"(c[1]), "+f"(c[2]), "+f"(c[3])
        : "r"(a0), "r"(a1), "r"(a2), "r"(a3), "r"(b0), "r"(b1));
}

__device__ __forceinline__ void ldsm_x4(
    uint32_t& r0, uint32_t& r1, uint32_t& r2, uint32_t& r3, const void* p)
{
    uint32_t a = (uint32_t)__cvta_generic_to_shared(p);
    asm volatile("ldmatrix.sync.aligned.m8n8.x4.shared.b16 {%0,%1,%2,%3}, [%4];"
        : "=r"(r0), "=r"(r1), "=r"(r2), "=r"(r3) : "r"(a));
}

__device__ __forceinline__ void ldsm_x4_t(
    uint32_t& r0, uint32_t& r1, uint32_t& r2, uint32_t& r3, const void* p)
{
    uint32_t a = (uint32_t)__cvta_generic_to_shared(p);
    asm volatile("ldmatrix.sync.aligned.m8n8.x4.trans.shared.b16 {%0,%1,%2,%3}, [%4];"
        : "=r"(r0), "=r"(r1), "=r"(r2), "=r"(r3) : "r"(a));
}

__device__ __forceinline__ void cp8(void* smem, const void* gmem) {
    uint32_t s = (uint32_t)__cvta_generic_to_shared(smem);
    asm volatile("cp.async.ca.shared.global [%0], [%1], 8;" :: "r"(s), "l"(gmem));
}

__device__ __forceinline__ uint2 pack4h(float4 v) {
    uint2 u;
    __half2 h;
    h = __floats2half2_rn(v.x, v.y); u.x = *(uint32_t*)&h;
    h = __floats2half2_rn(v.z, v.w); u.y = *(uint32_t*)&h;
    return u;
}

__device__ __forceinline__ uint32_t packh2(float a, float b) {
    __half2 h = __floats2half2_rn(a, b);
    return *(uint32_t*)&h;
}

// ---------------------------------------------------------------------------
// f32 -> f16 bulk conversions
// ---------------------------------------------------------------------------
__global__ __launch_bounds__(256) void f2h4(
    const float* __restrict__ src, __half* __restrict__ dst, int n4)
{
    for (int i = blockIdx.x * 256 + threadIdx.x; i < n4; i += gridDim.x * 256) {
        float4 v = ((const float4*)src)[i];
        ((uint2*)dst)[i] = pack4h(v);
    }
}

__global__ __launch_bounds__(256) void f2h4_w(
    const float* __restrict__ w0, const float* __restrict__ w1,
    const float* __restrict__ w2, const float* __restrict__ w3, int n4)
{
    const float* src = (blockIdx.y == 0) ? w0 : (blockIdx.y == 1) ? w1
                     : (blockIdx.y == 2) ? w2 : w3;
    __half* dst = (blockIdx.y == 0) ? g_wq : (blockIdx.y == 1) ? g_wk
                : (blockIdx.y == 2) ? g_wv : g_wo;
    for (int i = blockIdx.x * 256 + threadIdx.x; i < n4; i += gridDim.x * 256) {
        float4 v = ((const float4*)src)[i];
        ((uint2*)dst)[i] = pack4h(v);
    }
}

// ---------------------------------------------------------------------------
// Projection GEMM core (fp16 m16n8k16 + ldmatrix, half gmem operands,
// 1 sync/iter, reg double buffer). Block 128x128, BK=16, warp tile 64x32.
// ---------------------------------------------------------------------------
template <bool QKV>
__device__ __forceinline__ void gemm_core(
    const __half* __restrict__ Asrc, const __half* __restrict__ W,
    const float* __restrict__ bias, float* __restrict__ dstf,
    __half* __restrict__ dsth,
    int m0, int n0,
    __half (*As)[128][AST], __half (*Bs)[16][BST])
{
    const int tid = threadIdx.x;
    const int wid = tid >> 5, lane = tid & 31;
    const int gid = lane >> 2, tk = lane & 3;
    const int wm = (wid & 1) * 64;
    const int wn = (wid >> 1) * 32;
    const int l15 = lane & 15, lhi = (lane >> 4) * 8;

    const int arow = tid >> 1, ak8 = (tid & 1) * 8;
    const int bkr  = tid >> 4, bn8 = (tid & 15) * 8;
    const bool aval = (m0 + arow < M_);

    float acc[4][4][4];
    #pragma unroll
    for (int mi = 0; mi < 4; mi++)
        #pragma unroll
        for (int ni = 0; ni < 4; ni++)
            #pragma unroll
            for (int r = 0; r < 4; r++) acc[mi][ni][r] = 0.f;

    const uint4 z4 = make_uint4(0u, 0u, 0u, 0u);

    {
        uint4 va = z4;
        if (aval) va = *(const uint4*)(Asrc + (size_t)(m0 + arow) * D_ + ak8);
        uint4 vb = *(const uint4*)(W + (size_t)bkr * D_ + n0 + bn8);
        *(uint4*)&As[0][arow][ak8] = va;
        *(uint4*)&Bs[0][bkr][bn8]  = vb;
    }
    __syncthreads();

    const int NK = D_ / 16;   // 48
    for (int kt = 0; kt < NK; kt++) {
        const int cur = kt & 1;
        const bool pf = (kt + 1 < NK);
        uint4 va = z4, vb = z4;
        if (pf) {
            const int k1 = (kt + 1) * 16;
            if (aval) va = *(const uint4*)(Asrc + (size_t)(m0 + arow) * D_ + k1 + ak8);
            vb = *(const uint4*)(W + (size_t)(k1 + bkr) * D_ + n0 + bn8);
        }

        uint32_t af[4][4];
        #pragma unroll
        for (int mi = 0; mi < 4; mi++)
            ldsm_x4(af[mi][0], af[mi][1], af[mi][2], af[mi][3],
                    &As[cur][wm + mi * 16 + l15][lhi]);
        uint32_t bf[8];
        ldsm_x4_t(bf[0], bf[1], bf[2], bf[3], &Bs[cur][l15][wn + lhi]);
        ldsm_x4_t(bf[4], bf[5], bf[6], bf[7], &Bs[cur][l15][wn + 16 + lhi]);

        #pragma unroll
        for (int mi = 0; mi < 4; mi++) {
            hmma(acc[mi][0], af[mi][0], af[mi][1], af[mi][2], af[mi][3], bf[0], bf[1]);
            hmma(acc[mi][1], af[mi][0], af[mi][1], af[mi][2], af[mi][3], bf[2], bf[3]);
            hmma(acc[mi][2], af[mi][0], af[mi][1], af[mi][2], af[mi][3], bf[4], bf[5]);
            hmma(acc[mi][3], af[mi][0], af[mi][1], af[mi][2], af[mi][3], bf[6], bf[7]);
        }

        if (pf) {
            *(uint4*)&As[cur ^ 1][arow][ak8] = va;
            *(uint4*)&Bs[cur ^ 1][bkr][bn8]  = vb;
        }
        __syncthreads();
    }

    #pragma unroll
    for (int mi = 0; mi < 4; mi++) {
        #pragma unroll
        for (int ni = 0; ni < 4; ni++) {
            const int col = n0 + wn + ni * 8 + 2 * tk;
            const float b0v = bias[col], b1v = bias[col + 1];
            const int r0 = m0 + wm + mi * 16 + gid;
            const int r1 = r0 + 8;
            if (QKV) {
                const int h = col >> 6, hd = col & 63;
                if (r0 < M_) {
                    const int b = r0 / S_, s = r0 - b * S_;
                    *(uint32_t*)(dsth + (((size_t)(b * H_ + h)) * S_ + s) * HD_ + hd) =
                        packh2(acc[mi][ni][0] + b0v, acc[mi][ni][1] + b1v);
                }
                if (r1 < M_) {
                    const int b = r1 / S_, s = r1 - b * S_;
                    *(uint32_t*)(dsth + (((size_t)(b * H_ + h)) * S_ + s) * HD_ + hd) =
                        packh2(acc[mi][ni][2] + b0v, acc[mi][ni][3] + b1v);
                }
            } else {
                if (r0 < M_)
                    *(float2*)(dstf + (size_t)r0 * D_ + col) =
                        make_float2(acc[mi][ni][0] + b0v, acc[mi][ni][1] + b1v);
                if (r1 < M_)
                    *(float2*)(dstf + (size_t)r1 * D_ + col) =
                        make_float2(acc[mi][ni][2] + b0v, acc[mi][ni][3] + b1v);
            }
        }
    }
}

__global__ __launch_bounds__(256, 2) void gemm_qkv(
    const float* __restrict__ bq, const float* __restrict__ bk,
    const float* __restrict__ bv)
{
    __shared__ __align__(16) __half As[2][128][AST];
    __shared__ __align__(16) __half Bs[2][16][BST];
    const int m0  = blockIdx.x * 128;
    const int ng  = blockIdx.y * 128;
    const int mat = ng / D_;
    const int n0  = ng - mat * D_;
    const __half* W   = (mat == 0) ? g_wq : (mat == 1) ? g_wk : g_wv;
    const float* bias = (mat == 0) ? bq : (mat == 1) ? bk : bv;
    __half* dsth = (mat == 0) ? g_qh : (mat == 1) ? g_kh : g_vh;
    gemm_core<true>(g_xh, W, bias, nullptr, dsth, m0, n0, As, Bs);
}

__global__ __launch_bounds__(256, 2) void gemm_out(
    const float* __restrict__ bias, float* __restrict__ out)
{
    __shared__ __align__(16) __half As[2][128][AST];
    __shared__ __align__(16) __half Bs[2][16][BST];
    gemm_core<false>(g_ctxh, g_wo, bias, out, nullptr,
                     blockIdx.x * 128, blockIdx.y * 128, As, Bs);
}

// ---------------------------------------------------------------------------
// Fused attention, 64-row q tile, 512 threads.
//   scores: fp16 LDSM, K chunks double-buffered via cp.async (1 sync/chunk)
//   softmax: register-resident, half in-place output (V chunk0 prefetch hides
//            behind it)
//   ctx:    A via LDSM on Ph; V chunks double-buffered via cp.async
// SMEM: P[64][644] f32 + Qh[64][QSH] + KVh[2][128][QSH]  (~206 KB)
// ---------------------------------------------------------------------------
__global__ __launch_bounds__(512, 1) void fused_attn(
    float* __restrict__ probs, const int* __restrict__ mask)
{
    extern __shared__ float sm[];
    float*  P   = sm;                                   // [QT][PSTR] f32
    __half* Qh  = (__half*)(sm + QT * PSTR);            // [QT][QSH]
    __half* KV0 = Qh + QT * QSH;                        // buf 0: [128][QSH]
    __half* KV1 = KV0 + 128 * QSH;                      // buf 1: [128][QSH]

    const int bh  = blockIdx.y;
    const int m0  = blockIdx.x * QT;
    const int tid = threadIdx.x;
    const int wid = tid >> 5, lane = tid & 31;
    const int gid = lane >> 2, tk = lane & 3;
    const int wm  = (wid & 3) * 16;      // 4 warps along m (16 rows each) = 64
    const int wns = (wid >> 2) * 32;     // scores: 4 warps x 32 cols = 128
    const int wnc = (wid >> 2) * 16;     // ctx: 4 warps x 16 cols = 64
    const int l15 = lane & 15, lhi = (lane >> 4) * 8;
    const int brow = (lane & 7) + ((lane & 16) ? 8 : 0);
    const int bko  = (lane & 8) ? 8 : 0;
    const int b   = bh / H_;
    const int h   = bh - b * H_;

    const __half* qb = g_qh + (size_t)bh * S_ * HD_;
    const __half* kb = g_kh + (size_t)bh * S_ * HD_;
    const __half* vb = g_vh + (size_t)bh * S_ * HD_;
    float* pgm = probs + (size_t)bh * S_ * S_;

    // per-thread chunk-fill coordinates (4 x 8B per thread = 128x64 halves)
    const int frow[4] = { (tid + 0)   >> 4, (tid + 512) >> 4,
                          (tid + 1024) >> 4, (tid + 1536) >> 4 };
    const int fc4 = (tid & 15) << 2;

    // fill a 128-row chunk of src starting at gmem row `base` into buf
    auto fill_chunk = [&](__half* buf, const __half* src, int base) {
        #pragma unroll
        for (int i = 0; i < 4; i++) {
            const int row = frow[i];
            if (base + row < S_)
                cp8(&buf[row * QSH + fc4], src + (size_t)(base + row) * HD_ + fc4);
            else
                *(uint2*)&buf[row * QSH + fc4] = make_uint2(0u, 0u);
        }
    };

    // prologue: prefetch K chunk 0; load Q tile (regular)
    fill_chunk(KV0, kb, 0);
    asm volatile("cp.async.commit_group;");
    #pragma unroll
    for (int i = 0; i < 2; i++) {
        const int idx = tid + i * 512;
        const int row = idx >> 4, c4 = (idx & 15) << 2;
        uint2 v = make_uint2(0u, 0u);
        if (m0 + row < S_) v = *(const uint2*)(qb + (size_t)(m0 + row) * HD_ + c4);
        *(uint2*)&Qh[row * QSH + c4] = v;
    }
    asm volatile("cp.async.wait_group 0;");
    __syncthreads();

    // ---- scores phase: 5 chunks of 128 key-columns, double-buffered ----
    for (int nc = 0; nc < 5; nc++) {
        __half* cur = (nc & 1) ? KV1 : KV0;
        __half* nxt = (nc & 1) ? KV0 : KV1;
        if (nc + 1 < 5) {
            fill_chunk(nxt, kb, (nc + 1) * 128);
            asm volatile("cp.async.commit_group;");
        }

        const int n0 = nc * 128;
        float acc[4][4];
        #pragma unroll
        for (int ni = 0; ni < 4; ni++)
            #pragma unroll
            for (int r = 0; r < 4; r++) acc[ni][r] = 0.f;

        #pragma unroll
        for (int ks = 0; ks < 64; ks += 16) {
            uint32_t a0, a1, a2, a3;
            ldsm_x4(a0, a1, a2, a3, &Qh[(wm + l15) * QSH + ks + lhi]);
            #pragma unroll
            for (int nt = 0; nt < 2; nt++) {
                uint32_t b0, b1, b2, b3;
                ldsm_x4(b0, b1, b2, b3,
                        &cur[(wns + nt * 16 + brow) * QSH + ks + bko]);
                hmma(acc[nt * 2 + 0], a0, a1, a2, a3, b0, b1);
                hmma(acc[nt * 2 + 1], a0, a1, a2, a3, b2, b3);
            }
        }

        #pragma unroll
        for (int ni = 0; ni < 4; ni++) {
            const int col = n0 + wns + ni * 8 + 2 * tk;   // even
            if (col < S_) {
                *(float2*)&P[(wm + gid    ) * PSTR + col] =
                    make_float2(acc[ni][0] * 0.125f, acc[ni][1] * 0.125f);
                *(float2*)&P[(wm + gid + 8) * PSTR + col] =
                    make_float2(acc[ni][2] * 0.125f, acc[ni][3] * 0.125f);
            }
        }

        asm volatile("cp.async.wait_group 0;");
        __syncthreads();
    }

    // prefetch V chunk 0 (hides behind the whole softmax phase)
    fill_chunk(KV0, vb, 0);
    asm volatile("cp.async.commit_group;");

    // ---- softmax phase: register-resident; warp w owns rows w*4..w*4+3.
    //      Output written as HALF in place (Ph row r = front of f32 row r).
    #define NE 20   // ceil(626/32); covers columns 0..639 for padding
    for (int r = wid * 4; r < wid * 4 + 4; r++) {
        const int q = m0 + r;
        if (q >= S_) break;
        float* row = P + (size_t)r * PSTR;

        float e[NE];
        #pragma unroll
        for (int j = 0; j < NE; j++) {
            const int i = lane + 32 * j;
            e[j] = (i < S_) ? row[i] : -3.4e38f;
        }

        float mx = -3.4e38f;
        #pragma unroll
        for (int j = 0; j < NE; j++) mx = fmaxf(mx, e[j]);
        #pragma unroll
        for (int o = 16; o; o >>= 1) mx = fmaxf(mx, __shfl_xor_sync(0xffffffffu, mx, o));

        if (q == 0) {
            const float add = mx * 0.25f;
            #pragma unroll
            for (int j = 0; j < NE; j++) {
                const int i = lane + 32 * j;
                if (i < S_) {
                    const int mk = (i == 0) ? 0 : mask[b * SM1_ + i - 1];
                    if (mk == 0) e[j] += add;
                }
            }
            mx = -3.4e38f;
            #pragma unroll
            for (int j = 0; j < NE; j++) mx = fmaxf(mx, e[j]);
            #pragma unroll
            for (int o = 16; o; o >>= 1) mx = fmaxf(mx, __shfl_xor_sync(0xffffffffu, mx, o));
        }

        if (lane == 0) g_contrib[(size_t)bh * S_ + q] = e[0];   // fixed score at k=0

        float s = 0.f;
        #pragma unroll
        for (int j = 0; j < NE; j++) {
            const int i = lane + 32 * j;
            const float v = (i < S_) ? __expf(e[j] - mx) : 0.f;
            e[j] = v;
            s += v;
        }
        #pragma unroll
        for (int o = 16; o; o >>= 1) s += __shfl_xor_sync(0xffffffffu, s, o);
        const float inv = 1.0f / s;

        // ensure all f32 reads of this row precede the aliasing half writes
        asm volatile("" ::: "memory");

        __half* ph = (__half*)row;                    // overlays this row only
        float* prow = pgm + (size_t)q * S_;
        #pragma unroll
        for (int j = 0; j < NE; j++) {
            const int i = lane + 32 * j;
            if (i < S_) {
                const float p = e[j] * inv;
                ph[i] = __float2half_rn(p);
                prow[i] = p;
            } else {
                ph[i] = __float2half_rn(0.f * inv);   // pad cols 626..639
            }
        }
    }
    #undef NE
    asm volatile("cp.async.wait_group 0;");
    __syncthreads();

    // ---- ctx phase: 5 chunks of 128 k-rows, double-buffered ----
    float cacc[2][4];
    #pragma unroll
    for (int ni = 0; ni < 2; ni++)
        #pragma unroll
        for (int r = 0; r < 4; r++) cacc[ni][r] = 0.f;

    const __half* Ph = (const __half*)P;              // row stride 2*PSTR halves

    for (int kc = 0; kc < 5; kc++) {
        __half* cur = (kc & 1) ? KV1 : KV0;
        __half* nxt = (kc & 1) ? KV0 : KV1;
        if (kc + 1 < 5) {
            fill_chunk(nxt, vb, (kc + 1) * 128);
            asm volatile("cp.async.commit_group;");
        }

        const int k0 = kc * 128;
        #pragma unroll
        for (int ks = 0; ks < 128; ks += 16) {
            uint32_t a0, a1, a2, a3;
            ldsm_x4(a0, a1, a2, a3,
                    &Ph[(size_t)(wm + l15) * (2 * PSTR) + k0 + ks + lhi]);
            uint32_t b0, b1, b2, b3;
            ldsm_x4_t(b0, b1, b2, b3, &cur[(ks + l15) * QSH + wnc + lhi]);
            hmma(cacc[0], a0, a1, a2, a3, b0, b1);
            hmma(cacc[1], a0, a1, a2, a3, b2, b3);
        }

        if (kc + 1 < 5) {
            asm volatile("cp.async.wait_group 0;");
            __syncthreads();
        }
    }

    // ctx epilogue -> half (gemm_out reads half A)
    #pragma unroll
    for (int ni = 0; ni < 2; ni++) {
        const int col = wnc + ni * 8 + 2 * tk;   // even, 0..62
        const int r0 = m0 + wm + gid;
        const int r1 = r0 + 8;
        if (r0 < S_)
            *(uint32_t*)(g_ctxh + ((size_t)(b * S_ + r0)) * D_ + h * HD_ + col) =
                packh2(cacc[ni][0], cacc[ni][1]);
        if (r1 < S_)
            *(uint32_t*)(g_ctxh + ((size_t)(b * S_ + r1)) * D_ + h * HD_ + col) =
                packh2(cacc[ni][2], cacc[ni][3]);
    }
}

// ---------------------------------------------------------------------------
// Contribution: softmax over q of g_contrib[bh, :]
// ---------------------------------------------------------------------------
__global__ __launch_bounds__(256) void contrib_kernel(float* __restrict__ out)
{
    const int bh = blockIdx.x;
    const float* src = g_contrib + (size_t)bh * S_;
    __shared__ float red[8];
    const int tid = threadIdx.x;

    float m = -3.4e38f;
    for (int i = tid; i < S_; i += 256) m = fmaxf(m, src[i]);
    #pragma unroll
    for (int o = 16; o; o >>= 1) m = fmaxf(m, __shfl_xor_sync(0xffffffffu, m, o));
    if ((tid & 31) == 0) red[tid >> 5] = m;
    __syncthreads();
    if (tid == 0) {
        float mm = red[0];
        #pragma unroll
        for (int w = 1; w < 8; w++) mm = fmaxf(mm, red[w]);
        red[0] = mm;
    }
    __syncthreads();
    m = red[0];
    __syncthreads();

    float s = 0.f;
    for (int i = tid; i < S_; i += 256) s += expf(src[i] - m);
    #pragma unroll
    for (int o = 16; o; o >>= 1) s += __shfl_xor_sync(0xffffffffu, s, o);
    if ((tid & 31) == 0) red[tid >> 5] = s;
    __syncthreads();
    if (tid == 0) {
        float ss = 0.f;
        #pragma unroll
        for (int w = 0; w < 8; w++) ss += red[w];
        red[0] = ss;
    }
    __syncthreads();
    const float inv = 1.0f / red[0];
    for (int i = tid; i < S_; i += 256)
        out[(size_t)bh * S_ + i] = expf(src[i] - m) * inv;
}

// ---------------------------------------------------------------------------
// Launch
// ---------------------------------------------------------------------------
extern "C" void kernel_launch(void* const* d_in, const int* in_sizes, int n_in,
                              void* d_out, int out_size)
{
    const float* hs = (const float*)d_in[0];
    const int*  mask = (const int*) d_in[1];
    const float* Wq = (const float*)d_in[2];
    const float* bq = (const float*)d_in[3];
    const float* Wk = (const float*)d_in[4];
    const float* bk = (const float*)d_in[5];
    const float* Wv = (const float*)d_in[6];
    const float* bv = (const float*)d_in[7];
    const float* Wo = (const float*)d_in[8];
    const float* bo = (const float*)d_in[9];

    float* out     = (float*)d_out;
    float* att_out = out;                                       // [B,S,D]
    float* probs   = out + (size_t)M_ * D_;                     // [B,H,S,S]
    float* contrib = probs + (size_t)BH_ * S_ * S_;             // [B,H,S]

    // SMEM: P f32 + Qh half + KVh half x2 buffers
    const int smem_bytes = QT * PSTR * 4 + QT * QSH * 2 + 2 * 128 * QSH * 2;
    cudaFuncSetAttribute(fused_attn,
        cudaFuncAttributeMaxDynamicSharedMemorySize, smem_bytes);

    __half* xh;
    cudaGetSymbolAddress((void**)&xh, g_xh);

    const int nx4 = (M_ * D_) / 4;
    const int nw4 = (D_ * D_) / 4;
    f2h4<<<(nx4 + 255) / 256, 256>>>(hs, xh, nx4);
    f2h4_w<<<dim3(144, 4), 256>>>(Wq, Wk, Wv, Wo, nw4);

    gemm_qkv<<<dim3(79, 18), 256>>>(bq, bk, bv);
    fused_attn<<<dim3(10, 192), 512, smem_bytes>>>(probs, mask);
    contrib_kernel<<<BH_, 256>>>(contrib);
    gemm_out<<<dim3(79, 6), 256>>>(bo, att_out);
}